// round 5
// baseline (speedup 1.0000x reference)
#include <cuda_runtime.h>
#include <cstdint>

#define NN 100000
#define NE 400000
#define NG 1000
#define EPSV 1e-5f

__device__ float g_P[(size_t)NN * 256];
__device__ float g_Q[(size_t)NN * 256];
__device__ float g_h1[(size_t)NN * 128];
__device__ float g_h2[(size_t)NN * 256];
__device__ float g_h3[(size_t)NN * 256];
__device__ float g_e0[(size_t)NE * 256];
__device__ float g_e1[(size_t)NE * 128];
__device__ int   g_src[NE];
__device__ int   g_dst[NE];
__device__ int   g_batch[NN];
__device__ float g_deg[NN];
__device__ float g_invdeg[NN];
__device__ double g_sum[256];
__device__ double g_sumsq[256];
__device__ float g_alpha[256];
__device__ float g_beta[256];
__device__ float g_wt[256 * 256];
__device__ float g_wtA[256 * 256];
__device__ float g_wtB[256 * 256];
__device__ float g_pool[NG * 256];
__device__ float g_cnt[NG];
__device__ int   g_is64;

__device__ __forceinline__ float f2tf(float x) {
    uint32_t u;
    asm("cvt.rna.tf32.f32 %0, %1;" : "=r"(u) : "f"(x));
    return __uint_as_float(u);
}

// ---------------- setup kernels ----------------
__global__ void k_flag_init() { g_is64 = 1; }

__global__ void k_flag_check(const unsigned long long* __restrict__ e) {
    int i = blockIdx.x * blockDim.x + threadIdx.x;
    for (; i < NE; i += gridDim.x * blockDim.x)
        if (e[i] >= (unsigned long long)NN) g_is64 = 0;
}

__global__ void k_convert(const void* __restrict__ ei, const void* __restrict__ bt) {
    int i0 = blockIdx.x * blockDim.x + threadIdx.x;
    int st = gridDim.x * blockDim.x;
    int is64 = g_is64;
    for (int k = i0; k < NE; k += st) {
        int s, d;
        if (is64) {
            const long long* e = (const long long*)ei;
            s = (int)e[k]; d = (int)e[NE + k];
        } else {
            const int* e = (const int*)ei;
            s = e[k]; d = e[NE + k];
        }
        g_src[k] = s; g_dst[k] = d;
    }
    for (int k = i0; k < NN; k += st)
        g_batch[k] = is64 ? (int)((const long long*)bt)[k] : ((const int*)bt)[k];
}

__global__ void k_deg() {
    int i = blockIdx.x * blockDim.x + threadIdx.x;
    for (; i < NE; i += gridDim.x * blockDim.x) atomicAdd(&g_deg[g_dst[i]], 1.f);
}
__global__ void k_invdeg() {
    int i = blockIdx.x * blockDim.x + threadIdx.x;
    if (i < NN) g_invdeg[i] = 1.f / fmaxf(g_deg[i], 1.f);
}

// layer-1 of block 1: x[N,5] -> P = x@(Wtop-Wbot), Q = x@Wbot  [N,128]
__global__ void k_l1(const float* __restrict__ x, const float* __restrict__ W,
                     float* __restrict__ P, float* __restrict__ Qo) {
    __shared__ float wd[5 * 128], wb[5 * 128];
    int c = threadIdx.x;  // 128
#pragma unroll
    for (int k = 0; k < 5; k++) {
        float t = W[(5 + k) * 128 + c];
        wb[k * 128 + c] = t;
        wd[k * 128 + c] = W[k * 128 + c] - t;
    }
    __syncthreads();
    for (int n = blockIdx.x; n < NN; n += gridDim.x) {
        float xv[5];
#pragma unroll
        for (int k = 0; k < 5; k++) xv[k] = x[n * 5 + k];
        float p = 0.f, q = 0.f;
#pragma unroll
        for (int k = 0; k < 5; k++) {
            p = fmaf(xv[k], wd[k * 128 + c], p);
            q = fmaf(xv[k], wb[k * 128 + c], q);
        }
        P[(size_t)n * 128 + c] = p;
        Qo[(size_t)n * 128 + c] = q;
    }
}

// per-channel stats of h_e = P[dst]+Q[src]+b over edges
__global__ void k_pqstats(const float* __restrict__ P, const float* __restrict__ Qb,
                          const float* __restrict__ comb, int C) {
    int c = threadIdx.x;  // blockDim == C
    float bc = comb[c];
    float s = 0.f, q = 0.f;
    for (int e = blockIdx.x; e < NE; e += gridDim.x) {
        float v = P[(size_t)g_dst[e] * C + c] + Qb[(size_t)g_src[e] * C + c] + bc;
        s += v;
        q = fmaf(v, v, q);
    }
    atomicAdd(&g_sum[c], (double)s);
    atomicAdd(&g_sumsq[c], (double)q);
}

// GraphNorm -> per-channel affine (alpha,beta); resets accumulators
__global__ void k_finalize(const float* __restrict__ gn, int C) {
    int c = threadIdx.x;
    if (c < C) {
        float invE = 1.f / (float)NE;
        float m  = (float)(g_sum[c] * invE);
        float m2 = (float)(g_sumsq[c] * invE);
        float g = gn[c], b = gn[C + c], ms = gn[2 * C + c];
        float var = m2 - 2.f * ms * m * m + ms * ms * m * m;
        float rs = rsqrtf(var + EPSV);
        g_alpha[c] = g * rs;
        g_beta[c]  = b - g * rs * ms * m;
        g_sum[c] = 0.0;
        g_sumsq[c] = 0.0;
    }
}

__device__ __forceinline__ float afr(float v, int k) {
    return fmaxf(fmaf(g_alpha[k], v, g_beta[k]), 0.f);
}

// weight transpose: Wt[n*K+k] = W[k*N+n]
__global__ void k_tr(const float* __restrict__ W, float* __restrict__ Wt, int K, int N) {
    int i = blockIdx.x * blockDim.x + threadIdx.x;
    int tot = K * N;
    for (; i < tot; i += gridDim.x * blockDim.x) {
        int k = i / N, n = i % N;
        Wt[(size_t)n * K + k] = W[i];
    }
}
// split + transpose: W is [2K,N]; WtA = (top-bot)^T, WtB = bot^T
__global__ void k_wdt(const float* __restrict__ W, float* __restrict__ WtA,
                      float* __restrict__ WtB, int K, int N) {
    int i = blockIdx.x * blockDim.x + threadIdx.x;
    int tot = K * N;
    for (; i < tot; i += gridDim.x * blockDim.x) {
        int k = i / N, n = i % N;
        float top = W[i];
        float bot = W[(size_t)K * N + i];
        WtA[(size_t)n * K + k] = top - bot;
        WtB[(size_t)n * K + k] = bot;
    }
}

// ---------------- tf32 mma.sync GEMM ----------------
// C[M,N] = f(A)@W + bias, W given transposed (Wt[N,K], K-major).
// MODE 0: plain A.  MODE 1: relu(affine(A)).  MODE 2: relu(affine(P[dst]+Q[src]+comb)).
// STATS: accumulate per-channel sum/sumsq of C (requires M % 128 == 0).
// 256 threads; 8 warps as 2(M) x 4(N); warp tile 64x32; K chunk 32, double-buffered.
#define PITCH 36
#define BUFW (128 * PITCH)
#define SMB ((4 * BUFW + 256) * 4)

template <int MODE, bool STATS>
__global__ void __launch_bounds__(256)
wm_gemm(const float* __restrict__ A, const float* __restrict__ Qb,
        const float* __restrict__ Wt, const float* __restrict__ bias,
        const float* __restrict__ comb, float* __restrict__ Co,
        int M, int K, int N) {
    extern __shared__ float sm[];
    float* SA[2] = { sm, sm + 2 * BUFW };
    float* SB[2] = { sm + BUFW, sm + 3 * BUFW };
    float* Ssum = sm + 4 * BUFW;
    float* Ssq  = Ssum + 128;

    const int tid = threadIdx.x;
    const int wid = tid >> 5, lane = tid & 31;
    const int g = lane >> 2, t4 = lane & 3;
    const int warpM = wid & 1, warpN = wid >> 1;
    const int m0 = blockIdx.x * 128, n0 = blockIdx.y * 128;
    const int rw = tid >> 3, f = tid & 7;

    if (STATS && tid < 128) { Ssum[tid] = 0.f; Ssq[tid] = 0.f; }

    float c[4][4][4];
#pragma unroll
    for (int i = 0; i < 4; i++)
#pragma unroll
        for (int j = 0; j < 4; j++)
#pragma unroll
            for (int k = 0; k < 4; k++) c[i][j][k] = 0.f;

    const int nch = K >> 5;

    auto ld = [&](int ch, float4* va, float4* vb) {
        const int kg = (ch << 5) + f * 4;
#pragma unroll
        for (int p = 0; p < 4; p++) {
            int r = p * 32 + rw;
            int gm = m0 + r;
            float4 v = make_float4(0.f, 0.f, 0.f, 0.f);
            if (gm < M) {
                if (MODE == 0) {
                    v = *(const float4*)(A + (size_t)gm * K + kg);
                } else if (MODE == 1) {
                    float4 t = *(const float4*)(A + (size_t)gm * K + kg);
                    v.x = afr(t.x, kg);     v.y = afr(t.y, kg + 1);
                    v.z = afr(t.z, kg + 2); v.w = afr(t.w, kg + 3);
                } else {
                    int d = g_dst[gm], s = g_src[gm];
                    float4 pv = *(const float4*)(A + (size_t)d * K + kg);
                    float4 qv = *(const float4*)(Qb + (size_t)s * K + kg);
                    v.x = afr(pv.x + qv.x + comb[kg],     kg);
                    v.y = afr(pv.y + qv.y + comb[kg + 1], kg + 1);
                    v.z = afr(pv.z + qv.z + comb[kg + 2], kg + 2);
                    v.w = afr(pv.w + qv.w + comb[kg + 3], kg + 3);
                }
            }
            va[p] = v;
            vb[p] = *(const float4*)(Wt + (size_t)(n0 + r) * K + kg);
        }
    };
    auto st = [&](int ch, const float4* va, const float4* vb) {
        float* sa = SA[ch & 1];
        float* sb = SB[ch & 1];
#pragma unroll
        for (int p = 0; p < 4; p++) {
            int r = p * 32 + rw;
            float* a = sa + r * PITCH + f * 4;
            a[0] = f2tf(va[p].x); a[1] = f2tf(va[p].y);
            a[2] = f2tf(va[p].z); a[3] = f2tf(va[p].w);
            float* b = sb + r * PITCH + f * 4;
            b[0] = f2tf(vb[p].x); b[1] = f2tf(vb[p].y);
            b[2] = f2tf(vb[p].z); b[3] = f2tf(vb[p].w);
        }
    };
    auto comp = [&](int buf) {
        const float* sa = SA[buf];
        const float* sb = SB[buf];
#pragma unroll
        for (int ks = 0; ks < 4; ks++) {
            const int kk = ks * 8 + t4;
            float bf[4][2];
#pragma unroll
            for (int nf = 0; nf < 4; nf++) {
                int n = warpN * 32 + nf * 8 + g;
                bf[nf][0] = sb[n * PITCH + kk];
                bf[nf][1] = sb[n * PITCH + kk + 4];
            }
#pragma unroll
            for (int mf = 0; mf < 4; mf++) {
                int row = warpM * 64 + mf * 16 + g;
                float a0 = sa[row * PITCH + kk];
                float a1 = sa[(row + 8) * PITCH + kk];
                float a2 = sa[row * PITCH + kk + 4];
                float a3 = sa[(row + 8) * PITCH + kk + 4];
#pragma unroll
                for (int nf = 0; nf < 4; nf++) {
                    asm volatile(
                        "mma.sync.aligned.m16n8k8.row.col.f32.tf32.tf32.f32 "
                        "{%0,%1,%2,%3}, {%4,%5,%6,%7}, {%8,%9}, {%0,%1,%2,%3};"
                        : "+f"(c[mf][nf][0]), "+f"(c[mf][nf][1]),
                          "+f"(c[mf][nf][2]), "+f"(c[mf][nf][3])
                        : "r"(__float_as_uint(a0)), "r"(__float_as_uint(a1)),
                          "r"(__float_as_uint(a2)), "r"(__float_as_uint(a3)),
                          "r"(__float_as_uint(bf[nf][0])), "r"(__float_as_uint(bf[nf][1])));
                }
            }
        }
    };

    float4 va[4], vb[4];
    ld(0, va, vb);
    st(0, va, vb);
    __syncthreads();
    for (int ch = 0; ch < nch; ch++) {
        float4 na[4], nb[4];
        if (ch + 1 < nch) ld(ch + 1, na, nb);
        comp(ch & 1);
        if (ch + 1 < nch) st(ch + 1, na, nb);
        __syncthreads();
    }

    // epilogue
#pragma unroll
    for (int mf = 0; mf < 4; mf++) {
        int r0 = m0 + warpM * 64 + mf * 16 + g;
#pragma unroll
        for (int nf = 0; nf < 4; nf++) {
            int colL = warpN * 32 + nf * 8 + 2 * t4;
            int colg = n0 + colL;
            float b0 = bias ? bias[colg] : 0.f;
            float b1 = bias ? bias[colg + 1] : 0.f;
            float v0 = c[mf][nf][0] + b0, v1 = c[mf][nf][1] + b1;
            float v2 = c[mf][nf][2] + b0, v3 = c[mf][nf][3] + b1;
            if (r0 < M)     *(float2*)(Co + (size_t)r0 * N + colg)       = make_float2(v0, v1);
            if (r0 + 8 < M) *(float2*)(Co + (size_t)(r0 + 8) * N + colg) = make_float2(v2, v3);
            if (STATS) {
                atomicAdd(&Ssum[colL], v0 + v2);
                atomicAdd(&Ssum[colL + 1], v1 + v3);
                atomicAdd(&Ssq[colL], fmaf(v0, v0, v2 * v2));
                atomicAdd(&Ssq[colL + 1], fmaf(v1, v1, v3 * v3));
            }
        }
    }
    if (STATS) {
        __syncthreads();
        if (tid < 128) {
            atomicAdd(&g_sum[n0 + tid], (double)Ssum[tid]);
            atomicAdd(&g_sumsq[n0 + tid], (double)Ssq[tid]);
        }
    }
}

// ---------------- aggregation / pool / head ----------------
__global__ void k_agg_aff(const float* __restrict__ H, float* __restrict__ node, int logC) {
    int Cm = (1 << logC) - 1;
    size_t tot = (size_t)NE << logC;
    for (size_t idx = (size_t)blockIdx.x * blockDim.x + threadIdx.x; idx < tot;
         idx += (size_t)gridDim.x * blockDim.x) {
        int e = (int)(idx >> logC);
        int c = (int)(idx & Cm);
        float v = fmaxf(fmaf(g_alpha[c], H[idx], g_beta[c]), 0.f);
        atomicAdd(node + ((size_t)g_dst[e] << logC) + c, v);
    }
}

__global__ void k_agg_pq(const float* __restrict__ P, const float* __restrict__ Qb,
                         const float* __restrict__ comb, float* __restrict__ node, int logC) {
    int Cm = (1 << logC) - 1;
    size_t tot = (size_t)NE << logC;
    for (size_t idx = (size_t)blockIdx.x * blockDim.x + threadIdx.x; idx < tot;
         idx += (size_t)gridDim.x * blockDim.x) {
        int e = (int)(idx >> logC);
        int c = (int)(idx & Cm);
        int d = g_dst[e], s = g_src[e];
        float v = P[((size_t)d << logC) + c] + Qb[((size_t)s << logC) + c] + comb[c];
        v = fmaxf(fmaf(g_alpha[c], v, g_beta[c]), 0.f);
        atomicAdd(node + ((size_t)d << logC) + c, v);
    }
}

__global__ void k_scale(float* __restrict__ node, int logC) {
    size_t tot = (size_t)NN << logC;
    for (size_t idx = (size_t)blockIdx.x * blockDim.x + threadIdx.x; idx < tot;
         idx += (size_t)gridDim.x * blockDim.x)
        node[idx] *= g_invdeg[idx >> logC];
}

__global__ void k_pool(const float* __restrict__ h) {
    size_t tot = (size_t)NN * 256;
    for (size_t idx = (size_t)blockIdx.x * blockDim.x + threadIdx.x; idx < tot;
         idx += (size_t)gridDim.x * blockDim.x) {
        int n = (int)(idx >> 8);
        int c = (int)(idx & 255);
        int b = g_batch[n];
        atomicAdd(&g_pool[b * 256 + c], h[idx]);
        if (c == 0) atomicAdd(&g_cnt[b], 1.f);
    }
}

__global__ void k_head(const float* __restrict__ W1, const float* __restrict__ b1,
                       const float* __restrict__ W2, const float* __restrict__ b2,
                       float* __restrict__ out) {
    __shared__ float gv[256], hid[256], r0[256], r1[256];
    int r = blockIdx.x, t = threadIdx.x;
    float cnt = fmaxf(g_cnt[r], 1.f);
    gv[t] = g_pool[r * 256 + t] / cnt;
    __syncthreads();
    float a = b1[t];
    for (int k = 0; k < 256; k++) a = fmaf(gv[k], W1[k * 256 + t], a);
    hid[t] = fmaxf(a, 0.f);
    __syncthreads();
    r0[t] = hid[t] * W2[t * 2 + 0];
    r1[t] = hid[t] * W2[t * 2 + 1];
    __syncthreads();
    for (int s = 128; s > 0; s >>= 1) {
        if (t < s) { r0[t] += r0[t + s]; r1[t] += r1[t + s]; }
        __syncthreads();
    }
    if (t == 0) {
        out[r * 2 + 0] = r0[0] + b2[0];
        out[r * 2 + 1] = r1[0] + b2[1];
    }
}

// ---------------- launcher ----------------
extern "C" void kernel_launch(void* const* d_in, const int* in_sizes, int n_in,
                              void* d_out, int out_size) {
    const float* x      = (const float*)d_in[0];
    const void*  ei     = d_in[1];
    const void*  bt     = d_in[2];
    const float* c1_w1  = (const float*)d_in[3];
    const float* c1_b1  = (const float*)d_in[4];
    const float* c1_gn1 = (const float*)d_in[5];
    const float* c1_w2  = (const float*)d_in[6];
    const float* c1_b2  = (const float*)d_in[7];
    const float* c1_gn2 = (const float*)d_in[8];
    const float* c1_w3  = (const float*)d_in[9];
    const float* c1_b3  = (const float*)d_in[10];
    const float* c1_gn3 = (const float*)d_in[11];
    const float* c2_w1  = (const float*)d_in[12];
    const float* c2_b1  = (const float*)d_in[13];
    const float* c2_gn1 = (const float*)d_in[14];
    const float* c2_w2  = (const float*)d_in[15];
    const float* c2_b2  = (const float*)d_in[16];
    const float* c2_gn2 = (const float*)d_in[17];
    const float* c3_w1  = (const float*)d_in[18];
    const float* c3_b1  = (const float*)d_in[19];
    const float* c3_gn1 = (const float*)d_in[20];
    const float* lw1    = (const float*)d_in[21];
    const float* lb1    = (const float*)d_in[22];
    const float* lw2    = (const float*)d_in[23];
    const float* lb2    = (const float*)d_in[24];
    float* out = (float*)d_out;
    (void)in_sizes; (void)n_in; (void)out_size;

    float *pP, *pQ, *ph1, *ph2, *ph3, *pe0, *pe1, *pwt, *pwtA, *pwtB, *pdeg, *ppool, *pcnt;
    double *psum, *psq;
    cudaGetSymbolAddress((void**)&pP, g_P);
    cudaGetSymbolAddress((void**)&pQ, g_Q);
    cudaGetSymbolAddress((void**)&ph1, g_h1);
    cudaGetSymbolAddress((void**)&ph2, g_h2);
    cudaGetSymbolAddress((void**)&ph3, g_h3);
    cudaGetSymbolAddress((void**)&pe0, g_e0);
    cudaGetSymbolAddress((void**)&pe1, g_e1);
    cudaGetSymbolAddress((void**)&pwt, g_wt);
    cudaGetSymbolAddress((void**)&pwtA, g_wtA);
    cudaGetSymbolAddress((void**)&pwtB, g_wtB);
    cudaGetSymbolAddress((void**)&pdeg, g_deg);
    cudaGetSymbolAddress((void**)&ppool, g_pool);
    cudaGetSymbolAddress((void**)&pcnt, g_cnt);
    cudaGetSymbolAddress((void**)&psum, g_sum);
    cudaGetSymbolAddress((void**)&psq, g_sumsq);

    cudaFuncSetAttribute(wm_gemm<0, false>, cudaFuncAttributeMaxDynamicSharedMemorySize, SMB);
    cudaFuncSetAttribute(wm_gemm<1, true>,  cudaFuncAttributeMaxDynamicSharedMemorySize, SMB);
    cudaFuncSetAttribute(wm_gemm<2, true>,  cudaFuncAttributeMaxDynamicSharedMemorySize, SMB);

    // setup
    k_flag_init<<<1, 1>>>();
    k_flag_check<<<512, 256>>>((const unsigned long long*)ei);
    k_convert<<<1024, 256>>>(ei, bt);
    cudaMemsetAsync(pdeg, 0, NN * sizeof(float));
    k_deg<<<1024, 256>>>();
    k_invdeg<<<(NN + 255) / 256, 256>>>();
    cudaMemsetAsync(psum, 0, 256 * sizeof(double));
    cudaMemsetAsync(psq, 0, 256 * sizeof(double));

    const int ET = NE / 128;             // 3125 edge tiles
    const int NT = (NN + 127) / 128;     // 782 node tiles

    // block 1 (C=128, 3 layers)
    k_l1<<<2048, 128>>>(x, c1_w1, pP, pQ);
    k_pqstats<<<2048, 128>>>(pP, pQ, c1_b1, 128);
    k_finalize<<<1, 256>>>(c1_gn1, 128);
    k_tr<<<64, 256>>>(c1_w2, pwt, 128, 128);
    wm_gemm<2, true><<<dim3(ET, 1), 256, SMB>>>(pP, pQ, pwt, c1_b2, c1_b1, pe0, NE, 128, 128);
    k_finalize<<<1, 256>>>(c1_gn2, 128);
    k_tr<<<64, 256>>>(c1_w3, pwt, 128, 128);
    wm_gemm<1, true><<<dim3(ET, 1), 256, SMB>>>(pe0, nullptr, pwt, c1_b3, nullptr, pe1, NE, 128, 128);
    k_finalize<<<1, 256>>>(c1_gn3, 128);
    cudaMemsetAsync(ph1, 0, (size_t)NN * 128 * sizeof(float));
    k_agg_aff<<<16384, 256>>>(pe1, ph1, 7);
    k_scale<<<4096, 256>>>(ph1, 7);

    // block 2 (C=256, 2 layers)
    k_wdt<<<128, 256>>>(c2_w1, pwtA, pwtB, 128, 256);
    wm_gemm<0, false><<<dim3(NT, 2), 256, SMB>>>(ph1, nullptr, pwtA, nullptr, nullptr, pP, NN, 128, 256);
    wm_gemm<0, false><<<dim3(NT, 2), 256, SMB>>>(ph1, nullptr, pwtB, nullptr, nullptr, pQ, NN, 128, 256);
    k_pqstats<<<2048, 256>>>(pP, pQ, c2_b1, 256);
    k_finalize<<<1, 256>>>(c2_gn1, 256);
    k_tr<<<256, 256>>>(c2_w2, pwt, 256, 256);
    wm_gemm<2, true><<<dim3(ET, 2), 256, SMB>>>(pP, pQ, pwt, c2_b2, c2_b1, pe0, NE, 256, 256);
    k_finalize<<<1, 256>>>(c2_gn2, 256);
    cudaMemsetAsync(ph2, 0, (size_t)NN * 256 * sizeof(float));
    k_agg_aff<<<16384, 256>>>(pe0, ph2, 8);
    k_scale<<<8192, 256>>>(ph2, 8);

    // block 3 (C=256, 1 layer — no edge GEMM)
    k_wdt<<<256, 256>>>(c3_w1, pwtA, pwtB, 256, 256);
    wm_gemm<0, false><<<dim3(NT, 2), 256, SMB>>>(ph2, nullptr, pwtA, nullptr, nullptr, pP, NN, 256, 256);
    wm_gemm<0, false><<<dim3(NT, 2), 256, SMB>>>(ph2, nullptr, pwtB, nullptr, nullptr, pQ, NN, 256, 256);
    k_pqstats<<<2048, 256>>>(pP, pQ, c3_b1, 256);
    k_finalize<<<1, 256>>>(c3_gn1, 256);
    cudaMemsetAsync(ph3, 0, (size_t)NN * 256 * sizeof(float));
    k_agg_pq<<<16384, 256>>>(pP, pQ, c3_b1, ph3, 8);
    k_scale<<<8192, 256>>>(ph3, 8);

    // pool + head
    cudaMemsetAsync(ppool, 0, NG * 256 * sizeof(float));
    cudaMemsetAsync(pcnt, 0, NG * sizeof(float));
    k_pool<<<16384, 256>>>(ph3);
    k_head<<<NG, 256>>>(lw1, lb1, lw2, lb2, out);
}

// round 6
// speedup vs baseline: 1.2019x; 1.2019x over previous
#include <cuda_runtime.h>
#include <cstdint>

#define NN 100000
#define NE 400000
#define NG 1000
#define EPSV 1e-5f

__device__ float g_P[(size_t)NN * 256];
__device__ float g_Q[(size_t)NN * 256];
__device__ float g_h1[(size_t)NN * 128];
__device__ float g_h2[(size_t)NN * 256];
__device__ float g_h3[(size_t)NN * 256];
__device__ float g_e0[(size_t)NE * 256];
__device__ float g_e1[(size_t)NE * 128];
__device__ int   g_src[NE];
__device__ int   g_dst[NE];
__device__ int   g_batch[NN];
__device__ float g_deg[NN];
__device__ float g_invdeg[NN];
__device__ double g_sum[256];
__device__ double g_sumsq[256];
__device__ float g_alpha[256];
__device__ float g_beta[256];
__device__ float g_wt[256 * 256];
__device__ float g_wtA[256 * 256];
__device__ float g_wtB[256 * 256];
__device__ float g_pool[NG * 256];
__device__ float g_cnt[NG];
__device__ int   g_is64;

__device__ __forceinline__ float f2tf(float x) {
    uint32_t u;
    asm("cvt.rna.tf32.f32 %0, %1;" : "=r"(u) : "f"(x));
    return __uint_as_float(u);
}

// ---------------- setup kernels ----------------
__global__ void k_flag_init() { g_is64 = 1; }

__global__ void k_flag_check(const unsigned long long* __restrict__ e) {
    int i = blockIdx.x * blockDim.x + threadIdx.x;
    for (; i < NE; i += gridDim.x * blockDim.x)
        if (e[i] >= (unsigned long long)NN) g_is64 = 0;
}

__global__ void k_convert(const void* __restrict__ ei, const void* __restrict__ bt) {
    int i0 = blockIdx.x * blockDim.x + threadIdx.x;
    int st = gridDim.x * blockDim.x;
    int is64 = g_is64;
    for (int k = i0; k < NE; k += st) {
        int s, d;
        if (is64) {
            const long long* e = (const long long*)ei;
            s = (int)e[k]; d = (int)e[NE + k];
        } else {
            const int* e = (const int*)ei;
            s = e[k]; d = e[NE + k];
        }
        g_src[k] = s; g_dst[k] = d;
    }
    for (int k = i0; k < NN; k += st)
        g_batch[k] = is64 ? (int)((const long long*)bt)[k] : ((const int*)bt)[k];
}

__global__ void k_deg() {
    int i = blockIdx.x * blockDim.x + threadIdx.x;
    for (; i < NE; i += gridDim.x * blockDim.x) atomicAdd(&g_deg[g_dst[i]], 1.f);
}
__global__ void k_invdeg() {
    int i = blockIdx.x * blockDim.x + threadIdx.x;
    if (i < NN) g_invdeg[i] = 1.f / fmaxf(g_deg[i], 1.f);
}

// layer-1 of block 1: x[N,5] -> P = x@(Wtop-Wbot), Q = x@Wbot  [N,128]
__global__ void k_l1(const float* __restrict__ x, const float* __restrict__ W,
                     float* __restrict__ P, float* __restrict__ Qo) {
    __shared__ float wd[5 * 128], wb[5 * 128];
    int c = threadIdx.x;  // 128
#pragma unroll
    for (int k = 0; k < 5; k++) {
        float t = W[(5 + k) * 128 + c];
        wb[k * 128 + c] = t;
        wd[k * 128 + c] = W[k * 128 + c] - t;
    }
    __syncthreads();
    for (int n = blockIdx.x; n < NN; n += gridDim.x) {
        float xv[5];
#pragma unroll
        for (int k = 0; k < 5; k++) xv[k] = x[n * 5 + k];
        float p = 0.f, q = 0.f;
#pragma unroll
        for (int k = 0; k < 5; k++) {
            p = fmaf(xv[k], wd[k * 128 + c], p);
            q = fmaf(xv[k], wb[k * 128 + c], q);
        }
        P[(size_t)n * 128 + c] = p;
        Qo[(size_t)n * 128 + c] = q;
    }
}

// per-channel stats of h_e = P[dst]+Q[src]+b over edges
__global__ void k_pqstats(const float* __restrict__ P, const float* __restrict__ Qb,
                          const float* __restrict__ comb, int C) {
    int c = threadIdx.x;  // blockDim == C
    float bc = comb[c];
    float s = 0.f, q = 0.f;
    for (int e = blockIdx.x; e < NE; e += gridDim.x) {
        float v = P[(size_t)g_dst[e] * C + c] + Qb[(size_t)g_src[e] * C + c] + bc;
        s += v;
        q = fmaf(v, v, q);
    }
    atomicAdd(&g_sum[c], (double)s);
    atomicAdd(&g_sumsq[c], (double)q);
}

// GraphNorm -> per-channel affine (alpha,beta); resets accumulators
__global__ void k_finalize(const float* __restrict__ gn, int C) {
    int c = threadIdx.x;
    if (c < C) {
        float invE = 1.f / (float)NE;
        float m  = (float)(g_sum[c] * invE);
        float m2 = (float)(g_sumsq[c] * invE);
        float g = gn[c], b = gn[C + c], ms = gn[2 * C + c];
        float var = m2 - 2.f * ms * m * m + ms * ms * m * m;
        float rs = rsqrtf(var + EPSV);
        g_alpha[c] = g * rs;
        g_beta[c]  = b - g * rs * ms * m;
        g_sum[c] = 0.0;
        g_sumsq[c] = 0.0;
    }
}

// weight transpose: Wt[n*K+k] = W[k*N+n]
__global__ void k_tr(const float* __restrict__ W, float* __restrict__ Wt, int K, int N) {
    int i = blockIdx.x * blockDim.x + threadIdx.x;
    int tot = K * N;
    for (; i < tot; i += gridDim.x * blockDim.x) {
        int k = i / N, n = i % N;
        Wt[(size_t)n * K + k] = W[i];
    }
}
// split + transpose: W is [2K,N]; WtA = (top-bot)^T, WtB = bot^T
__global__ void k_wdt(const float* __restrict__ W, float* __restrict__ WtA,
                      float* __restrict__ WtB, int K, int N) {
    int i = blockIdx.x * blockDim.x + threadIdx.x;
    int tot = K * N;
    for (; i < tot; i += gridDim.x * blockDim.x) {
        int k = i / N, n = i % N;
        float top = W[i];
        float bot = W[(size_t)K * N + i];
        WtA[(size_t)n * K + k] = top - bot;
        WtB[(size_t)n * K + k] = bot;
    }
}

// ---------------- tf32 mma.sync GEMM (fragment-permuted smem) ----------------
// C[M,N] = f(A)@W + bias, W given transposed (Wt[N,K], K-major).
// MODE 0: plain A.  MODE 1: relu(affine(A)).  MODE 2: relu(affine(P[dst]+Q[src]+comb)).
// STATS: accumulate per-channel sum/sumsq of C.
// 256 threads = 8 warps as 2(M) x 4(N); warp tile 64x32; K chunk 32, single buffer.
// SMEM layout stores fragments directly: A float4 per (warpM,ks,mf,lane),
// B float2 per (warpN,ks,nf,lane) -> consumer does 1 LDS.128 / LDS.64 per fragment.
template <int MODE, bool STATS>
__global__ void __launch_bounds__(256, 2)
wm_gemm(const float* __restrict__ A, const float* __restrict__ Qb,
        const float* __restrict__ Wt, const float* __restrict__ bias,
        const float* __restrict__ comb, float* __restrict__ Co,
        int M, int K, int N) {
    __shared__ float sA[4096];   // 2 warpM * 4 ks * 4 mf * 32 lanes * 4
    __shared__ float sB[4096];   // 4 warpN * 4 ks * 4 nf * 32 lanes * 2
    __shared__ float Ssum[128], Ssq[128];

    const int tid = threadIdx.x;
    const int w = tid >> 5, lane = tid & 31;
    const int g = lane >> 2, t4 = lane & 3;
    const int warpM = w & 1, warpN = w >> 1;
    const int m0 = blockIdx.x * 128, n0 = blockIdx.y * 128;

    if (STATS && tid < 128) { Ssum[tid] = 0.f; Ssq[tid] = 0.f; }

    float c[4][4][4];
#pragma unroll
    for (int i = 0; i < 4; i++)
#pragma unroll
        for (int j = 0; j < 4; j++)
#pragma unroll
            for (int k = 0; k < 4; k++) c[i][j][k] = 0.f;

    // producer per-lane constants: this lane always handles k-offset = lane in chunk
    const int pks = lane >> 3;          // which ks block
    const int phi = (lane >> 2) & 1;    // k lo/hi half within ks block
    const int pt4 = lane & 3;

    const int nch = K >> 5;
    for (int ch = 0; ch < nch; ch++) {
        const int kgl = (ch << 5) + lane;
        float al = 1.f, bb = 0.f;
        if (MODE > 0) {
            al = g_alpha[kgl];
            bb = g_beta[kgl];
            if (MODE == 2) bb = fmaf(al, comb[kgl], bb);
        }
        // -------- produce: warp w fills rows w*16 .. w*16+15 of A and B tiles
#pragma unroll 8
        for (int j = 0; j < 16; j++) {
            const int r = w * 16 + j;
            const int gm = m0 + r;
            float v = 0.f;
            if (gm < M) {
                if (MODE == 0) {
                    v = A[(size_t)gm * K + kgl];
                } else if (MODE == 1) {
                    v = fmaxf(fmaf(al, A[(size_t)gm * K + kgl], bb), 0.f);
                } else {
                    int d = g_dst[gm], s = g_src[gm];
                    float raw = A[(size_t)d * K + kgl] + Qb[(size_t)s * K + kgl];
                    v = fmaxf(fmaf(al, raw, bb), 0.f);
                }
            }
            v = f2tf(v);
            const int wm = r >> 6, ri = r & 63, mf = ri >> 4, rb = ri & 15;
            sA[(((((wm << 2) + pks) << 2) + mf) * 32 + ((rb & 7) << 2) + pt4) * 4 +
               (phi << 1) + (rb >> 3)] = v;

            float bv = f2tf(Wt[(size_t)(n0 + r) * K + kgl]);
            const int wn = r >> 5, ni = r & 31, nf = ni >> 3;
            sB[(((((wn << 2) + pks) << 2) + nf) * 32 + ((ni & 7) << 2) + pt4) * 2 + phi] = bv;
        }
        __syncthreads();
        // -------- consume
        const float4* AP = (const float4*)sA;
        const float2* BP = (const float2*)sB;
#pragma unroll
        for (int ks = 0; ks < 4; ks++) {
            float4 af[4];
            float2 bf[4];
#pragma unroll
            for (int mf = 0; mf < 4; mf++)
                af[mf] = AP[((((warpM << 2) + ks) << 2) + mf) * 32 + lane];
#pragma unroll
            for (int nf = 0; nf < 4; nf++)
                bf[nf] = BP[((((warpN << 2) + ks) << 2) + nf) * 32 + lane];
#pragma unroll
            for (int mf = 0; mf < 4; mf++)
#pragma unroll
                for (int nf = 0; nf < 4; nf++) {
                    asm volatile(
                        "mma.sync.aligned.m16n8k8.row.col.f32.tf32.tf32.f32 "
                        "{%0,%1,%2,%3}, {%4,%5,%6,%7}, {%8,%9}, {%0,%1,%2,%3};"
                        : "+f"(c[mf][nf][0]), "+f"(c[mf][nf][1]),
                          "+f"(c[mf][nf][2]), "+f"(c[mf][nf][3])
                        : "r"(__float_as_uint(af[mf].x)), "r"(__float_as_uint(af[mf].y)),
                          "r"(__float_as_uint(af[mf].z)), "r"(__float_as_uint(af[mf].w)),
                          "r"(__float_as_uint(bf[nf].x)), "r"(__float_as_uint(bf[nf].y)));
                }
        }
        __syncthreads();
    }

    // -------- epilogue
#pragma unroll
    for (int mf = 0; mf < 4; mf++) {
        int r0 = m0 + warpM * 64 + mf * 16 + g;
#pragma unroll
        for (int nf = 0; nf < 4; nf++) {
            int colL = warpN * 32 + nf * 8 + 2 * t4;
            int colg = n0 + colL;
            float b0 = bias ? bias[colg] : 0.f;
            float b1 = bias ? bias[colg + 1] : 0.f;
            float v0 = c[mf][nf][0] + b0, v1 = c[mf][nf][1] + b1;
            float v2 = c[mf][nf][2] + b0, v3 = c[mf][nf][3] + b1;
            if (r0 < M)     *(float2*)(Co + (size_t)r0 * N + colg)       = make_float2(v0, v1);
            if (r0 + 8 < M) *(float2*)(Co + (size_t)(r0 + 8) * N + colg) = make_float2(v2, v3);
            if (STATS) {
                atomicAdd(&Ssum[colL], v0 + v2);
                atomicAdd(&Ssum[colL + 1], v1 + v3);
                atomicAdd(&Ssq[colL], fmaf(v0, v0, v2 * v2));
                atomicAdd(&Ssq[colL + 1], fmaf(v1, v1, v3 * v3));
            }
        }
    }
    if (STATS) {
        __syncthreads();
        if (tid < 128) {
            atomicAdd(&g_sum[n0 + tid], (double)Ssum[tid]);
            atomicAdd(&g_sumsq[n0 + tid], (double)Ssq[tid]);
        }
    }
}

// ---------------- aggregation / pool / head ----------------
__global__ void k_agg_aff(const float* __restrict__ H, float* __restrict__ node, int logC) {
    int Cm = (1 << logC) - 1;
    size_t tot = (size_t)NE << logC;
    for (size_t idx = (size_t)blockIdx.x * blockDim.x + threadIdx.x; idx < tot;
         idx += (size_t)gridDim.x * blockDim.x) {
        int e = (int)(idx >> logC);
        int c = (int)(idx & Cm);
        float v = fmaxf(fmaf(g_alpha[c], H[idx], g_beta[c]), 0.f);
        atomicAdd(node + ((size_t)g_dst[e] << logC) + c, v);
    }
}

__global__ void k_agg_pq(const float* __restrict__ P, const float* __restrict__ Qb,
                         const float* __restrict__ comb, float* __restrict__ node, int logC) {
    int Cm = (1 << logC) - 1;
    size_t tot = (size_t)NE << logC;
    for (size_t idx = (size_t)blockIdx.x * blockDim.x + threadIdx.x; idx < tot;
         idx += (size_t)gridDim.x * blockDim.x) {
        int e = (int)(idx >> logC);
        int c = (int)(idx & Cm);
        int d = g_dst[e], s = g_src[e];
        float v = P[((size_t)d << logC) + c] + Qb[((size_t)s << logC) + c] + comb[c];
        v = fmaxf(fmaf(g_alpha[c], v, g_beta[c]), 0.f);
        atomicAdd(node + ((size_t)d << logC) + c, v);
    }
}

__global__ void k_scale(float* __restrict__ node, int logC) {
    size_t tot = (size_t)NN << logC;
    for (size_t idx = (size_t)blockIdx.x * blockDim.x + threadIdx.x; idx < tot;
         idx += (size_t)gridDim.x * blockDim.x)
        node[idx] *= g_invdeg[idx >> logC];
}

__global__ void k_pool(const float* __restrict__ h) {
    size_t tot = (size_t)NN * 256;
    for (size_t idx = (size_t)blockIdx.x * blockDim.x + threadIdx.x; idx < tot;
         idx += (size_t)gridDim.x * blockDim.x) {
        int n = (int)(idx >> 8);
        int c = (int)(idx & 255);
        int b = g_batch[n];
        atomicAdd(&g_pool[b * 256 + c], h[idx]);
        if (c == 0) atomicAdd(&g_cnt[b], 1.f);
    }
}

__global__ void k_head(const float* __restrict__ W1, const float* __restrict__ b1,
                       const float* __restrict__ W2, const float* __restrict__ b2,
                       float* __restrict__ out) {
    __shared__ float gv[256], hid[256], r0[256], r1[256];
    int r = blockIdx.x, t = threadIdx.x;
    float cnt = fmaxf(g_cnt[r], 1.f);
    gv[t] = g_pool[r * 256 + t] / cnt;
    __syncthreads();
    float a = b1[t];
    for (int k = 0; k < 256; k++) a = fmaf(gv[k], W1[k * 256 + t], a);
    hid[t] = fmaxf(a, 0.f);
    __syncthreads();
    r0[t] = hid[t] * W2[t * 2 + 0];
    r1[t] = hid[t] * W2[t * 2 + 1];
    __syncthreads();
    for (int s = 128; s > 0; s >>= 1) {
        if (t < s) { r0[t] += r0[t + s]; r1[t] += r1[t + s]; }
        __syncthreads();
    }
    if (t == 0) {
        out[r * 2 + 0] = r0[0] + b2[0];
        out[r * 2 + 1] = r1[0] + b2[1];
    }
}

// ---------------- launcher ----------------
extern "C" void kernel_launch(void* const* d_in, const int* in_sizes, int n_in,
                              void* d_out, int out_size) {
    const float* x      = (const float*)d_in[0];
    const void*  ei     = d_in[1];
    const void*  bt     = d_in[2];
    const float* c1_w1  = (const float*)d_in[3];
    const float* c1_b1  = (const float*)d_in[4];
    const float* c1_gn1 = (const float*)d_in[5];
    const float* c1_w2  = (const float*)d_in[6];
    const float* c1_b2  = (const float*)d_in[7];
    const float* c1_gn2 = (const float*)d_in[8];
    const float* c1_w3  = (const float*)d_in[9];
    const float* c1_b3  = (const float*)d_in[10];
    const float* c1_gn3 = (const float*)d_in[11];
    const float* c2_w1  = (const float*)d_in[12];
    const float* c2_b1  = (const float*)d_in[13];
    const float* c2_gn1 = (const float*)d_in[14];
    const float* c2_w2  = (const float*)d_in[15];
    const float* c2_b2  = (const float*)d_in[16];
    const float* c2_gn2 = (const float*)d_in[17];
    const float* c3_w1  = (const float*)d_in[18];
    const float* c3_b1  = (const float*)d_in[19];
    const float* c3_gn1 = (const float*)d_in[20];
    const float* lw1    = (const float*)d_in[21];
    const float* lb1    = (const float*)d_in[22];
    const float* lw2    = (const float*)d_in[23];
    const float* lb2    = (const float*)d_in[24];
    float* out = (float*)d_out;
    (void)in_sizes; (void)n_in; (void)out_size;

    float *pP, *pQ, *ph1, *ph2, *ph3, *pe0, *pe1, *pwt, *pwtA, *pwtB, *pdeg, *ppool, *pcnt;
    double *psum, *psq;
    cudaGetSymbolAddress((void**)&pP, g_P);
    cudaGetSymbolAddress((void**)&pQ, g_Q);
    cudaGetSymbolAddress((void**)&ph1, g_h1);
    cudaGetSymbolAddress((void**)&ph2, g_h2);
    cudaGetSymbolAddress((void**)&ph3, g_h3);
    cudaGetSymbolAddress((void**)&pe0, g_e0);
    cudaGetSymbolAddress((void**)&pe1, g_e1);
    cudaGetSymbolAddress((void**)&pwt, g_wt);
    cudaGetSymbolAddress((void**)&pwtA, g_wtA);
    cudaGetSymbolAddress((void**)&pwtB, g_wtB);
    cudaGetSymbolAddress((void**)&pdeg, g_deg);
    cudaGetSymbolAddress((void**)&ppool, g_pool);
    cudaGetSymbolAddress((void**)&pcnt, g_cnt);
    cudaGetSymbolAddress((void**)&psum, g_sum);
    cudaGetSymbolAddress((void**)&psq, g_sumsq);

    // setup
    k_flag_init<<<1, 1>>>();
    k_flag_check<<<512, 256>>>((const unsigned long long*)ei);
    k_convert<<<1024, 256>>>(ei, bt);
    cudaMemsetAsync(pdeg, 0, NN * sizeof(float));
    k_deg<<<1024, 256>>>();
    k_invdeg<<<(NN + 255) / 256, 256>>>();
    cudaMemsetAsync(psum, 0, 256 * sizeof(double));
    cudaMemsetAsync(psq, 0, 256 * sizeof(double));

    const int ET = NE / 128;             // 3125 edge tiles
    const int NT = (NN + 127) / 128;     // 782 node tiles

    // block 1 (C=128, 3 layers)
    k_l1<<<2048, 128>>>(x, c1_w1, pP, pQ);
    k_pqstats<<<2048, 128>>>(pP, pQ, c1_b1, 128);
    k_finalize<<<1, 256>>>(c1_gn1, 128);
    k_tr<<<64, 256>>>(c1_w2, pwt, 128, 128);
    wm_gemm<2, true><<<dim3(ET, 1), 256>>>(pP, pQ, pwt, c1_b2, c1_b1, pe0, NE, 128, 128);
    k_finalize<<<1, 256>>>(c1_gn2, 128);
    k_tr<<<64, 256>>>(c1_w3, pwt, 128, 128);
    wm_gemm<1, true><<<dim3(ET, 1), 256>>>(pe0, nullptr, pwt, c1_b3, nullptr, pe1, NE, 128, 128);
    k_finalize<<<1, 256>>>(c1_gn3, 128);
    cudaMemsetAsync(ph1, 0, (size_t)NN * 128 * sizeof(float));
    k_agg_aff<<<16384, 256>>>(pe1, ph1, 7);
    k_scale<<<4096, 256>>>(ph1, 7);

    // block 2 (C=256, 2 layers)
    k_wdt<<<128, 256>>>(c2_w1, pwtA, pwtB, 128, 256);
    wm_gemm<0, false><<<dim3(NT, 2), 256>>>(ph1, nullptr, pwtA, nullptr, nullptr, pP, NN, 128, 256);
    wm_gemm<0, false><<<dim3(NT, 2), 256>>>(ph1, nullptr, pwtB, nullptr, nullptr, pQ, NN, 128, 256);
    k_pqstats<<<2048, 256>>>(pP, pQ, c2_b1, 256);
    k_finalize<<<1, 256>>>(c2_gn1, 256);
    k_tr<<<256, 256>>>(c2_w2, pwt, 256, 256);
    wm_gemm<2, true><<<dim3(ET, 2), 256>>>(pP, pQ, pwt, c2_b2, c2_b1, pe0, NE, 256, 256);
    k_finalize<<<1, 256>>>(c2_gn2, 256);
    cudaMemsetAsync(ph2, 0, (size_t)NN * 256 * sizeof(float));
    k_agg_aff<<<16384, 256>>>(pe0, ph2, 8);
    k_scale<<<8192, 256>>>(ph2, 8);

    // block 3 (C=256, 1 layer — no edge GEMM)
    k_wdt<<<256, 256>>>(c3_w1, pwtA, pwtB, 256, 256);
    wm_gemm<0, false><<<dim3(NT, 2), 256>>>(ph2, nullptr, pwtA, nullptr, nullptr, pP, NN, 256, 256);
    wm_gemm<0, false><<<dim3(NT, 2), 256>>>(ph2, nullptr, pwtB, nullptr, nullptr, pQ, NN, 256, 256);
    k_pqstats<<<2048, 256>>>(pP, pQ, c3_b1, 256);
    k_finalize<<<1, 256>>>(c3_gn1, 256);
    cudaMemsetAsync(ph3, 0, (size_t)NN * 256 * sizeof(float));
    k_agg_pq<<<16384, 256>>>(pP, pQ, c3_b1, ph3, 8);
    k_scale<<<8192, 256>>>(ph3, 8);

    // pool + head
    cudaMemsetAsync(ppool, 0, NG * 256 * sizeof(float));
    cudaMemsetAsync(pcnt, 0, NG * sizeof(float));
    k_pool<<<16384, 256>>>(ph3);
    k_head<<<NG, 256>>>(lw1, lb1, lw2, lb2, out);
}

// round 7
// speedup vs baseline: 1.8859x; 1.5692x over previous
#include <cuda_runtime.h>
#include <cuda_fp16.h>
#include <cstdint>

#define NN 100000
#define NE 400000
#define NG 1000
#define EPSV 1e-5f

__device__ __half g_P[(size_t)NN * 256];
__device__ __half g_Q[(size_t)NN * 256];
__device__ float  g_h1[(size_t)NN * 128];
__device__ float  g_h2[(size_t)NN * 256];
__device__ float  g_h3[(size_t)NN * 256];
__device__ __half g_e0[(size_t)NE * 256];
__device__ __half g_e1[(size_t)NE * 128];
__device__ int    g_src[NE];
__device__ int    g_dst[NE];
__device__ int    g_batch[NN];
__device__ float  g_deg[NN];
__device__ float  g_invdeg[NN];
__device__ double g_sum[256];
__device__ double g_sumsq[256];
__device__ float  g_alpha[256];
__device__ float  g_beta[256];
__device__ float  g_wt[256 * 256];
__device__ float  g_wtA[256 * 256];
__device__ float  g_wtB[256 * 256];
__device__ float  g_pool[NG * 256];
__device__ float  g_cnt[NG];
__device__ int    g_is64;

__device__ __forceinline__ void red4(float* p, float v0, float v1, float v2, float v3) {
    asm volatile("red.global.add.v4.f32 [%0], {%1,%2,%3,%4};"
                 :: "l"(p), "f"(v0), "f"(v1), "f"(v2), "f"(v3) : "memory");
}
__device__ __forceinline__ uint32_t h2u(__half2 h) { return *reinterpret_cast<uint32_t*>(&h); }
__device__ __forceinline__ __half2 u2h(uint32_t u) { return *reinterpret_cast<__half2*>(&u); }

// ---------------- setup ----------------
__global__ void k_flag_init() { g_is64 = 1; }

__global__ void k_flag_check(const unsigned long long* __restrict__ e) {
    int i = blockIdx.x * blockDim.x + threadIdx.x;
    for (; i < NE; i += gridDim.x * blockDim.x)
        if (e[i] >= (unsigned long long)NN) g_is64 = 0;
}

__global__ void k_convert(const void* __restrict__ ei, const void* __restrict__ bt) {
    int i0 = blockIdx.x * blockDim.x + threadIdx.x;
    int st = gridDim.x * blockDim.x;
    int is64 = g_is64;
    for (int k = i0; k < NE; k += st) {
        int s, d;
        if (is64) {
            const long long* e = (const long long*)ei;
            s = (int)e[k]; d = (int)e[NE + k];
        } else {
            const int* e = (const int*)ei;
            s = e[k]; d = e[NE + k];
        }
        g_src[k] = s; g_dst[k] = d;
    }
    for (int k = i0; k < NN; k += st)
        g_batch[k] = is64 ? (int)((const long long*)bt)[k] : ((const int*)bt)[k];
}

__global__ void k_deg() {
    int i = blockIdx.x * blockDim.x + threadIdx.x;
    for (; i < NE; i += gridDim.x * blockDim.x) atomicAdd(&g_deg[g_dst[i]], 1.f);
}
__global__ void k_invdeg() {
    int i = blockIdx.x * blockDim.x + threadIdx.x;
    if (i < NN) g_invdeg[i] = 1.f / fmaxf(g_deg[i], 1.f);
}
__global__ void k_cnt() {
    int i = blockIdx.x * blockDim.x + threadIdx.x;
    if (i < NN) atomicAdd(&g_cnt[g_batch[i]], 1.f);
}

// layer-1 of block 1: x[N,5] -> P = x@(Wtop-Wbot), Q = x@Wbot  [N,128] (fp16 out)
__global__ void k_l1(const float* __restrict__ x, const float* __restrict__ W) {
    __shared__ float wd[5 * 128], wb[5 * 128];
    int c = threadIdx.x;  // 128
#pragma unroll
    for (int k = 0; k < 5; k++) {
        float t = W[(5 + k) * 128 + c];
        wb[k * 128 + c] = t;
        wd[k * 128 + c] = W[k * 128 + c] - t;
    }
    __syncthreads();
    for (int n = blockIdx.x; n < NN; n += gridDim.x) {
        float xv[5];
#pragma unroll
        for (int k = 0; k < 5; k++) xv[k] = x[n * 5 + k];
        float p = 0.f, q = 0.f;
#pragma unroll
        for (int k = 0; k < 5; k++) {
            p = fmaf(xv[k], wd[k * 128 + c], p);
            q = fmaf(xv[k], wb[k * 128 + c], q);
        }
        g_P[(size_t)n * 128 + c] = __float2half_rn(p);
        g_Q[(size_t)n * 128 + c] = __float2half_rn(q);
    }
}

// per-channel stats of h_e = P[dst]+Q[src]+b over edges (half inputs)
__global__ void k_pqstats(const __half* __restrict__ P, const __half* __restrict__ Qb,
                          const float* __restrict__ comb, int C) {
    int c = threadIdx.x;  // blockDim == C
    float bc = comb[c];
    float s = 0.f, q = 0.f;
    for (int e = blockIdx.x; e < NE; e += gridDim.x) {
        float v = __half2float(P[(size_t)g_dst[e] * C + c]) +
                  __half2float(Qb[(size_t)g_src[e] * C + c]) + bc;
        s += v;
        q = fmaf(v, v, q);
    }
    atomicAdd(&g_sum[c], (double)s);
    atomicAdd(&g_sumsq[c], (double)q);
}

// GraphNorm -> per-channel affine (alpha,beta); resets accumulators
__global__ void k_finalize(const float* __restrict__ gn, int C) {
    int c = threadIdx.x;
    if (c < C) {
        float invE = 1.f / (float)NE;
        float m  = (float)(g_sum[c] * invE);
        float m2 = (float)(g_sumsq[c] * invE);
        float g = gn[c], b = gn[C + c], ms = gn[2 * C + c];
        float var = m2 - 2.f * ms * m * m + ms * ms * m * m;
        float rs = rsqrtf(var + EPSV);
        g_alpha[c] = g * rs;
        g_beta[c]  = b - g * rs * ms * m;
        g_sum[c] = 0.0;
        g_sumsq[c] = 0.0;
    }
}

// weight transpose: Wt[n*K+k] = W[k*N+n]
__global__ void k_tr(const float* __restrict__ W, float* __restrict__ Wt, int K, int N) {
    int i = blockIdx.x * blockDim.x + threadIdx.x;
    int tot = K * N;
    for (; i < tot; i += gridDim.x * blockDim.x) {
        int k = i / N, n = i % N;
        Wt[(size_t)n * K + k] = W[i];
    }
}
// split + transpose: W is [2K,N]; WtA = (top-bot)^T, WtB = bot^T
__global__ void k_wdt(const float* __restrict__ W, float* __restrict__ WtA,
                      float* __restrict__ WtB, int K, int N) {
    int i = blockIdx.x * blockDim.x + threadIdx.x;
    int tot = K * N;
    for (; i < tot; i += gridDim.x * blockDim.x) {
        int k = i / N, n = i % N;
        float top = W[i];
        float bot = W[(size_t)K * N + i];
        WtA[(size_t)n * K + k] = top - bot;
        WtB[(size_t)n * K + k] = bot;
    }
}

// ---------------- fp16 mma.sync GEMM (fragment-permuted smem) ----------------
// C[M,N] = f(A)@W + bias -> half out. Wt[N,K] fp32 K-major.
// MODE 1: A = half edge buffer, f = relu(affine(A)).
// MODE 2: f = relu(affine(P[dst]+Q[src]+comb)), A=P (half), Qb (half).
// MODE 3: A = fp32 node buffer scaled by invdeg (plain).
// STATS: accumulate per-channel sum/sumsq of outputs.
template <int MODE, bool STATS>
__global__ void __launch_bounds__(256, 2)
wm_gemm(const void* __restrict__ Ain, const __half* __restrict__ Qb,
        const float* __restrict__ Wt, const float* __restrict__ bias,
        const float* __restrict__ comb, __half* __restrict__ Co,
        int M, int K, int N) {
    __shared__ uint32_t sAu[2048];  // 8KB: A frags (half2-packed)
    __shared__ uint32_t sBu[2048];  // 8KB: B frags
    __shared__ float Ssum[128], Ssq[128];

    const int tid = threadIdx.x;
    const int w = tid >> 5, lane = tid & 31;
    const int g = lane >> 2, t4 = lane & 3;
    const int warpM = w & 1, warpN = w >> 1;
    const int m0 = blockIdx.x * 128, n0 = blockIdx.y * 128;

    if (STATS && tid < 128) { Ssum[tid] = 0.f; Ssq[tid] = 0.f; }

    float c[4][4][4];
#pragma unroll
    for (int i = 0; i < 4; i++)
#pragma unroll
        for (int j = 0; j < 4; j++)
#pragma unroll
            for (int k = 0; k < 4; k++) c[i][j][k] = 0.f;

    const int kpair = lane & 15;          // k = 2*kpair within 32-chunk
    const int rhalf = lane >> 4;
    const int ksP   = kpair >> 3;
    const int khi8  = (kpair >> 2) & 1;
    const int t4P   = kpair & 3;

    const int nch = K >> 5;
    for (int ch = 0; ch < nch; ch++) {
        const int kg = (ch << 5) + (kpair << 1);
        float2 alv = make_float2(1.f, 1.f), bev = make_float2(0.f, 0.f);
        if (MODE == 1 || MODE == 2) {
            alv = *(const float2*)(g_alpha + kg);
            bev = *(const float2*)(g_beta + kg);
            if (MODE == 2) {
                float2 cb = *(const float2*)(comb + kg);
                bev.x = fmaf(alv.x, cb.x, bev.x);
                bev.y = fmaf(alv.y, cb.y, bev.y);
            }
        }
#pragma unroll
        for (int j = 0; j < 8; j++) {
            const int r = (w << 4) + (j << 1) + rhalf;
            const int gm = m0 + r;
            float v0 = 0.f, v1 = 0.f;
            if (gm < M) {
                if (MODE == 3) {
                    float2 t = *(const float2*)((const float*)Ain + (size_t)gm * K + kg);
                    float s = g_invdeg[gm];
                    v0 = t.x * s; v1 = t.y * s;
                } else if (MODE == 1) {
                    float2 f = __half22float2(*(const __half2*)((const __half*)Ain + (size_t)gm * K + kg));
                    v0 = fmaxf(fmaf(alv.x, f.x, bev.x), 0.f);
                    v1 = fmaxf(fmaf(alv.y, f.y, bev.y), 0.f);
                } else {
                    int d = g_dst[gm], s = g_src[gm];
                    float2 fp = __half22float2(*(const __half2*)((const __half*)Ain + (size_t)d * K + kg));
                    float2 fq = __half22float2(*(const __half2*)(Qb + (size_t)s * K + kg));
                    v0 = fmaxf(fmaf(alv.x, fp.x + fq.x, bev.x), 0.f);
                    v1 = fmaxf(fmaf(alv.y, fp.y + fq.y, bev.y), 0.f);
                }
            }
            uint32_t hu = h2u(__floats2half2_rn(v0, v1));
            const int rb = r & 15, mf = (r >> 4) & 3, wm = r >> 6;
            const int gA = rb & 7, rowhi = rb >> 3;
            sAu[((((wm << 1) + ksP) << 2) + mf) * 128 + (gA << 4) + (t4P << 2) + rowhi + (khi8 << 1)] = hu;

            float2 wv = *(const float2*)(Wt + (size_t)(n0 + r) * K + kg);
            uint32_t bu = h2u(__floats2half2_rn(wv.x, wv.y));
            const int ni = r & 31, wn = r >> 5, nf = ni >> 3, gB = ni & 7;
            sBu[((((wn << 1) + ksP) << 2) + nf) * 64 + (gB << 3) + (t4P << 1) + khi8] = bu;
        }
        __syncthreads();
        const uint4* A4 = (const uint4*)sAu;
        const uint2* B2 = (const uint2*)sBu;
#pragma unroll
        for (int ks = 0; ks < 2; ks++) {
            uint4 af[4];
            uint2 bf[4];
#pragma unroll
            for (int mf = 0; mf < 4; mf++)
                af[mf] = A4[((((warpM << 1) + ks) << 2) + mf) * 32 + lane];
#pragma unroll
            for (int nf = 0; nf < 4; nf++)
                bf[nf] = B2[((((warpN << 1) + ks) << 2) + nf) * 32 + lane];
#pragma unroll
            for (int mf = 0; mf < 4; mf++)
#pragma unroll
                for (int nf = 0; nf < 4; nf++) {
                    asm volatile(
                        "mma.sync.aligned.m16n8k16.row.col.f32.f16.f16.f32 "
                        "{%0,%1,%2,%3}, {%4,%5,%6,%7}, {%8,%9}, {%0,%1,%2,%3};"
                        : "+f"(c[mf][nf][0]), "+f"(c[mf][nf][1]),
                          "+f"(c[mf][nf][2]), "+f"(c[mf][nf][3])
                        : "r"(af[mf].x), "r"(af[mf].y), "r"(af[mf].z), "r"(af[mf].w),
                          "r"(bf[nf].x), "r"(bf[nf].y));
                }
        }
        __syncthreads();
    }

    // epilogue
#pragma unroll
    for (int mf = 0; mf < 4; mf++) {
        int r0 = m0 + warpM * 64 + mf * 16 + g;
#pragma unroll
        for (int nf = 0; nf < 4; nf++) {
            int colL = warpN * 32 + nf * 8 + 2 * t4;
            int colg = n0 + colL;
            float b0 = bias ? bias[colg] : 0.f;
            float b1 = bias ? bias[colg + 1] : 0.f;
            float v0 = c[mf][nf][0] + b0, v1 = c[mf][nf][1] + b1;
            float v2 = c[mf][nf][2] + b0, v3 = c[mf][nf][3] + b1;
            if (r0 < M)
                *(__half2*)(Co + (size_t)r0 * N + colg) = __floats2half2_rn(v0, v1);
            if (r0 + 8 < M)
                *(__half2*)(Co + (size_t)(r0 + 8) * N + colg) = __floats2half2_rn(v2, v3);
            if (STATS) {
                atomicAdd(&Ssum[colL], v0 + v2);
                atomicAdd(&Ssum[colL + 1], v1 + v3);
                atomicAdd(&Ssq[colL], fmaf(v0, v0, v2 * v2));
                atomicAdd(&Ssq[colL + 1], fmaf(v1, v1, v3 * v3));
            }
        }
    }
    if (STATS) {
        __syncthreads();
        if (tid < 128) {
            atomicAdd(&g_sum[n0 + tid], (double)Ssum[tid]);
            atomicAdd(&g_sumsq[n0 + tid], (double)Ssq[tid]);
        }
    }
}

// ---------------- aggregation / pool / head ----------------
// scatter relu(affine(H)) (half edge buf) to dst nodes; 4 channels/thread, red.v4
__global__ void k_agg_aff(const __half* __restrict__ H, float* __restrict__ node, int logC) {
    const int sh = logC - 2;
    size_t tot = (size_t)NE << sh;
    for (size_t idx = (size_t)blockIdx.x * blockDim.x + threadIdx.x; idx < tot;
         idx += (size_t)gridDim.x * blockDim.x) {
        int e = (int)(idx >> sh);
        int cc = ((int)idx & ((1 << sh) - 1)) << 2;
        uint2 hv = *(const uint2*)(H + ((size_t)e << logC) + cc);
        float2 f01 = __half22float2(u2h(hv.x));
        float2 f23 = __half22float2(u2h(hv.y));
        float4 al = *(const float4*)(g_alpha + cc);
        float4 be = *(const float4*)(g_beta + cc);
        float v0 = fmaxf(fmaf(al.x, f01.x, be.x), 0.f);
        float v1 = fmaxf(fmaf(al.y, f01.y, be.y), 0.f);
        float v2 = fmaxf(fmaf(al.z, f23.x, be.z), 0.f);
        float v3 = fmaxf(fmaf(al.w, f23.y, be.w), 0.f);
        red4(node + ((size_t)g_dst[e] << logC) + cc, v0, v1, v2, v3);
    }
}

// block-3 path: scatter relu(affine(P[dst]+Q[src]+comb)) without edge GEMM
__global__ void k_agg_pq(const __half* __restrict__ P, const __half* __restrict__ Qb,
                         const float* __restrict__ comb, float* __restrict__ node, int logC) {
    const int sh = logC - 2;
    size_t tot = (size_t)NE << sh;
    for (size_t idx = (size_t)blockIdx.x * blockDim.x + threadIdx.x; idx < tot;
         idx += (size_t)gridDim.x * blockDim.x) {
        int e = (int)(idx >> sh);
        int cc = ((int)idx & ((1 << sh) - 1)) << 2;
        int d = g_dst[e], s = g_src[e];
        uint2 pv = *(const uint2*)(P + ((size_t)d << logC) + cc);
        uint2 qv = *(const uint2*)(Qb + ((size_t)s << logC) + cc);
        float2 p01 = __half22float2(u2h(pv.x)), p23 = __half22float2(u2h(pv.y));
        float2 q01 = __half22float2(u2h(qv.x)), q23 = __half22float2(u2h(qv.y));
        float4 al = *(const float4*)(g_alpha + cc);
        float4 be = *(const float4*)(g_beta + cc);
        float4 cb = *(const float4*)(comb + cc);
        float v0 = fmaxf(fmaf(al.x, p01.x + q01.x + cb.x, be.x), 0.f);
        float v1 = fmaxf(fmaf(al.y, p01.y + q01.y + cb.y, be.y), 0.f);
        float v2 = fmaxf(fmaf(al.z, p23.x + q23.x + cb.z, be.z), 0.f);
        float v3 = fmaxf(fmaf(al.w, p23.y + q23.y + cb.w, be.w), 0.f);
        red4(node + ((size_t)d << logC) + cc, v0, v1, v2, v3);
    }
}

// pool: mean over nodes per graph; invdeg folded here (h3 holds edge-sums)
__global__ void k_pool(const float* __restrict__ h) {
    size_t tot = (size_t)NN * 64;
    for (size_t idx = (size_t)blockIdx.x * blockDim.x + threadIdx.x; idx < tot;
         idx += (size_t)gridDim.x * blockDim.x) {
        int n = (int)(idx >> 6);
        int cc = ((int)idx & 63) << 2;
        float4 v = *(const float4*)(h + (size_t)n * 256 + cc);
        float s = g_invdeg[n];
        red4(g_pool + (size_t)g_batch[n] * 256 + cc, v.x * s, v.y * s, v.z * s, v.w * s);
    }
}

__global__ void k_head(const float* __restrict__ W1, const float* __restrict__ b1,
                       const float* __restrict__ W2, const float* __restrict__ b2,
                       float* __restrict__ out) {
    __shared__ float gv[256], hid[256], r0[256], r1[256];
    int r = blockIdx.x, t = threadIdx.x;
    float cnt = fmaxf(g_cnt[r], 1.f);
    gv[t] = g_pool[r * 256 + t] / cnt;
    __syncthreads();
    float a = b1[t];
    for (int k = 0; k < 256; k++) a = fmaf(gv[k], W1[k * 256 + t], a);
    hid[t] = fmaxf(a, 0.f);
    __syncthreads();
    r0[t] = hid[t] * W2[t * 2 + 0];
    r1[t] = hid[t] * W2[t * 2 + 1];
    __syncthreads();
    for (int s = 128; s > 0; s >>= 1) {
        if (t < s) { r0[t] += r0[t + s]; r1[t] += r1[t + s]; }
        __syncthreads();
    }
    if (t == 0) {
        out[r * 2 + 0] = r0[0] + b2[0];
        out[r * 2 + 1] = r1[0] + b2[1];
    }
}

// ---------------- launcher ----------------
extern "C" void kernel_launch(void* const* d_in, const int* in_sizes, int n_in,
                              void* d_out, int out_size) {
    const float* x      = (const float*)d_in[0];
    const void*  ei     = d_in[1];
    const void*  bt     = d_in[2];
    const float* c1_w1  = (const float*)d_in[3];
    const float* c1_b1  = (const float*)d_in[4];
    const float* c1_gn1 = (const float*)d_in[5];
    const float* c1_w2  = (const float*)d_in[6];
    const float* c1_b2  = (const float*)d_in[7];
    const float* c1_gn2 = (const float*)d_in[8];
    const float* c1_w3  = (const float*)d_in[9];
    const float* c1_b3  = (const float*)d_in[10];
    const float* c1_gn3 = (const float*)d_in[11];
    const float* c2_w1  = (const float*)d_in[12];
    const float* c2_b1  = (const float*)d_in[13];
    const float* c2_gn1 = (const float*)d_in[14];
    const float* c2_w2  = (const float*)d_in[15];
    const float* c2_b2  = (const float*)d_in[16];
    const float* c2_gn2 = (const float*)d_in[17];
    const float* c3_w1  = (const float*)d_in[18];
    const float* c3_b1  = (const float*)d_in[19];
    const float* c3_gn1 = (const float*)d_in[20];
    const float* lw1    = (const float*)d_in[21];
    const float* lb1    = (const float*)d_in[22];
    const float* lw2    = (const float*)d_in[23];
    const float* lb2    = (const float*)d_in[24];
    float* out = (float*)d_out;
    (void)in_sizes; (void)n_in; (void)out_size;

    __half *pP, *pQ, *pe0, *pe1;
    float *ph1, *ph2, *ph3, *pwt, *pwtA, *pwtB, *pdeg, *ppool, *pcnt;
    double *psum, *psq;
    cudaGetSymbolAddress((void**)&pP, g_P);
    cudaGetSymbolAddress((void**)&pQ, g_Q);
    cudaGetSymbolAddress((void**)&ph1, g_h1);
    cudaGetSymbolAddress((void**)&ph2, g_h2);
    cudaGetSymbolAddress((void**)&ph3, g_h3);
    cudaGetSymbolAddress((void**)&pe0, g_e0);
    cudaGetSymbolAddress((void**)&pe1, g_e1);
    cudaGetSymbolAddress((void**)&pwt, g_wt);
    cudaGetSymbolAddress((void**)&pwtA, g_wtA);
    cudaGetSymbolAddress((void**)&pwtB, g_wtB);
    cudaGetSymbolAddress((void**)&pdeg, g_deg);
    cudaGetSymbolAddress((void**)&ppool, g_pool);
    cudaGetSymbolAddress((void**)&pcnt, g_cnt);
    cudaGetSymbolAddress((void**)&psum, g_sum);
    cudaGetSymbolAddress((void**)&psq, g_sumsq);

    // setup
    k_flag_init<<<1, 1>>>();
    k_flag_check<<<512, 256>>>((const unsigned long long*)ei);
    k_convert<<<1024, 256>>>(ei, bt);
    cudaMemsetAsync(pdeg, 0, NN * sizeof(float));
    k_deg<<<1024, 256>>>();
    k_invdeg<<<(NN + 255) / 256, 256>>>();
    cudaMemsetAsync(psum, 0, 256 * sizeof(double));
    cudaMemsetAsync(psq, 0, 256 * sizeof(double));

    const int ET = NE / 128;             // 3125 edge tiles
    const int NT = (NN + 127) / 128;     // 782 node tiles

    // block 1 (C=128, 3 layers)
    k_l1<<<2048, 128>>>(x, c1_w1);
    k_pqstats<<<2048, 128>>>(pP, pQ, c1_b1, 128);
    k_finalize<<<1, 256>>>(c1_gn1, 128);
    k_tr<<<64, 256>>>(c1_w2, pwt, 128, 128);
    wm_gemm<2, true><<<dim3(ET, 1), 256>>>(pP, pQ, pwt, c1_b2, c1_b1, pe0, NE, 128, 128);
    k_finalize<<<1, 256>>>(c1_gn2, 128);
    k_tr<<<64, 256>>>(c1_w3, pwt, 128, 128);
    wm_gemm<1, true><<<dim3(ET, 1), 256>>>(pe0, nullptr, pwt, c1_b3, nullptr, pe1, NE, 128, 128);
    k_finalize<<<1, 256>>>(c1_gn3, 128);
    cudaMemsetAsync(ph1, 0, (size_t)NN * 128 * sizeof(float));
    k_agg_aff<<<8192, 256>>>(pe1, ph1, 7);

    // block 2 (C=256, 2 layers); invdeg folded into MODE 3 producers
    k_wdt<<<128, 256>>>(c2_w1, pwtA, pwtB, 128, 256);
    wm_gemm<3, false><<<dim3(NT, 2), 256>>>(ph1, nullptr, pwtA, nullptr, nullptr, pP, NN, 128, 256);
    wm_gemm<3, false><<<dim3(NT, 2), 256>>>(ph1, nullptr, pwtB, nullptr, nullptr, pQ, NN, 128, 256);
    k_pqstats<<<2048, 256>>>(pP, pQ, c2_b1, 256);
    k_finalize<<<1, 256>>>(c2_gn1, 256);
    k_tr<<<256, 256>>>(c2_w2, pwt, 256, 256);
    wm_gemm<2, true><<<dim3(ET, 2), 256>>>(pP, pQ, pwt, c2_b2, c2_b1, pe0, NE, 256, 256);
    k_finalize<<<1, 256>>>(c2_gn2, 256);
    cudaMemsetAsync(ph2, 0, (size_t)NN * 256 * sizeof(float));
    k_agg_aff<<<8192, 256>>>(pe0, ph2, 8);

    // block 3 (C=256, 1 layer — no edge GEMM)
    k_wdt<<<256, 256>>>(c3_w1, pwtA, pwtB, 256, 256);
    wm_gemm<3, false><<<dim3(NT, 2), 256>>>(ph2, nullptr, pwtA, nullptr, nullptr, pP, NN, 256, 256);
    wm_gemm<3, false><<<dim3(NT, 2), 256>>>(ph2, nullptr, pwtB, nullptr, nullptr, pQ, NN, 256, 256);
    k_pqstats<<<2048, 256>>>(pP, pQ, c3_b1, 256);
    k_finalize<<<1, 256>>>(c3_gn1, 256);
    cudaMemsetAsync(ph3, 0, (size_t)NN * 256 * sizeof(float));
    k_agg_pq<<<8192, 256>>>(pP, pQ, c3_b1, ph3, 8);

    // pool + head (invdeg folded into k_pool)
    cudaMemsetAsync(ppool, 0, NG * 256 * sizeof(float));
    cudaMemsetAsync(pcnt, 0, NG * sizeof(float));
    k_cnt<<<(NN + 255) / 256, 256>>>();
    k_pool<<<4096, 256>>>(ph3);
    k_head<<<NG, 256>>>(lw1, lb1, lw2, lb2, out);
}

// round 8
// speedup vs baseline: 2.2699x; 1.2036x over previous
#include <cuda_runtime.h>
#include <cuda_fp16.h>
#include <cstdint>

#define NN 100000
#define NE 400000
#define NG 1000
#define EPSV 1e-5f

__device__ __half g_P[(size_t)NN * 256];
__device__ __half g_Q[(size_t)NN * 256];
__device__ __half g_h1[(size_t)NN * 128];
__device__ __half g_h2[(size_t)NN * 256];
__device__ __half g_h3[(size_t)NN * 256];
__device__ __half g_e0[(size_t)NE * 256];
__device__ __half g_e1[(size_t)NE * 128];
__device__ int    g_src[NE];
__device__ int    g_dst[NE];
__device__ int    g_ssrc[NE];
__device__ int    g_sdst[NE];
__device__ int    g_batch[NN];
__device__ int    g_hist[NN];
__device__ int    g_seg[NN + 1];
__device__ int    g_cur[NN];
__device__ int    g_ghist[NG];
__device__ int    g_gseg[NG + 1];
__device__ float  g_invdeg[NN];
__device__ double g_sum[256];
__device__ double g_sumsq[256];
__device__ float  g_alpha[256];
__device__ float  g_beta[256];
__device__ uint32_t g_wtp [2 * 8 * 2048];
__device__ uint32_t g_wtpA[2 * 8 * 2048];
__device__ uint32_t g_wtpB[2 * 8 * 2048];
__device__ float  g_pool[NG * 256];

__device__ __forceinline__ uint32_t h2u(__half2 h) { return *reinterpret_cast<uint32_t*>(&h); }

// ---------------- convert + histograms (is64 detected per-block) ----------------
__global__ void k_convert(const void* __restrict__ ei, const void* __restrict__ bt) {
    __shared__ int s64;
    if (threadIdx.x == 0) {
        const unsigned long long* e = (const unsigned long long*)ei;
        int f = 1;
        for (int i = 0; i < 256; i++)
            if (e[i] >= (unsigned long long)NN) { f = 0; break; }
        s64 = f;
    }
    __syncthreads();
    const int is64 = s64;
    int i0 = blockIdx.x * blockDim.x + threadIdx.x;
    int st = gridDim.x * blockDim.x;
    for (int k = i0; k < NE; k += st) {
        int s, d;
        if (is64) {
            const long long* e = (const long long*)ei;
            s = (int)e[k]; d = (int)e[NE + k];
        } else {
            const int* e = (const int*)ei;
            s = e[k]; d = e[NE + k];
        }
        g_src[k] = s; g_dst[k] = d;
        atomicAdd(&g_hist[d], 1);
    }
    for (int k = i0; k < NN; k += st) {
        int b = is64 ? (int)((const long long*)bt)[k] : ((const int*)bt)[k];
        g_batch[k] = b;
        atomicAdd(&g_ghist[b], 1);
    }
}

// single-block exclusive scan over node histogram -> CSR offsets (+invdeg)
__global__ void k_scan_nodes() {
    __shared__ int sb[1024];
    __shared__ int carry;
    int t = threadIdx.x;
    if (t == 0) carry = 0;
    __syncthreads();
    for (int base = 0; base < NN; base += 1024) {
        int i = base + t;
        int v = (i < NN) ? g_hist[i] : 0;
        sb[t] = v;
        __syncthreads();
        for (int off = 1; off < 1024; off <<= 1) {
            int x = sb[t];
            int y = (t >= off) ? sb[t - off] : 0;
            __syncthreads();
            sb[t] = x + y;
            __syncthreads();
        }
        int excl = sb[t] - v;
        int c = carry;
        if (i < NN) {
            g_seg[i] = c + excl;
            g_cur[i] = c + excl;
            g_invdeg[i] = 1.f / fmaxf((float)v, 1.f);
        }
        __syncthreads();
        if (t == 1023) carry += sb[1023];
        __syncthreads();
    }
    if (t == 0) g_seg[NN] = carry;
}

__global__ void k_scan_graphs() {
    __shared__ int sb[1024];
    int t = threadIdx.x;
    int v = (t < NG) ? g_ghist[t] : 0;
    sb[t] = v;
    __syncthreads();
    for (int off = 1; off < 1024; off <<= 1) {
        int x = sb[t];
        int y = (t >= off) ? sb[t - off] : 0;
        __syncthreads();
        sb[t] = x + y;
        __syncthreads();
    }
    if (t < NG) g_gseg[t] = sb[t] - v;
    if (t == 1023) g_gseg[NG] = sb[1023];
}

__global__ void k_scatter() {
    int i = blockIdx.x * blockDim.x + threadIdx.x;
    for (; i < NE; i += gridDim.x * blockDim.x) {
        int d = g_dst[i];
        int p = atomicAdd(&g_cur[d], 1);
        g_ssrc[p] = g_src[i];
        g_sdst[p] = d;
    }
}

// layer-1 of block 1: x[N,5] -> P = x@(Wtop-Wbot), Q = x@Wbot  [N,128] fp16
__global__ void k_l1(const float* __restrict__ x, const float* __restrict__ W) {
    __shared__ float wd[5 * 128], wb[5 * 128];
    int c = threadIdx.x;
#pragma unroll
    for (int k = 0; k < 5; k++) {
        float t = W[(5 + k) * 128 + c];
        wb[k * 128 + c] = t;
        wd[k * 128 + c] = W[k * 128 + c] - t;
    }
    __syncthreads();
    for (int n = blockIdx.x; n < NN; n += gridDim.x) {
        float xv[5];
#pragma unroll
        for (int k = 0; k < 5; k++) xv[k] = x[n * 5 + k];
        float p = 0.f, q = 0.f;
#pragma unroll
        for (int k = 0; k < 5; k++) {
            p = fmaf(xv[k], wd[k * 128 + c], p);
            q = fmaf(xv[k], wb[k * 128 + c], q);
        }
        g_P[(size_t)n * 128 + c] = __float2half_rn(p);
        g_Q[(size_t)n * 128 + c] = __float2half_rn(q);
    }
}

// per-channel stats of h_e = P[dst]+Q[src]+b over sorted edges
__global__ void k_pqstats(const __half* __restrict__ P, const __half* __restrict__ Qb,
                          const float* __restrict__ comb, int C) {
    int c = threadIdx.x;
    float bc = comb[c];
    int L = (NE + gridDim.x - 1) / gridDim.x;
    int e0 = blockIdx.x * L;
    int e1 = min(e0 + L, NE);
    float s = 0.f, q = 0.f;
    for (int e = e0; e < e1; e++) {
        float v = __half2float(P[(size_t)g_sdst[e] * C + c]) +
                  __half2float(Qb[(size_t)g_ssrc[e] * C + c]) + bc;
        s += v;
        q = fmaf(v, v, q);
    }
    atomicAdd(&g_sum[c], (double)s);
    atomicAdd(&g_sumsq[c], (double)q);
}

__global__ void k_finalize(const float* __restrict__ gn, int C) {
    int c = threadIdx.x;
    if (c < C) {
        float invE = 1.f / (float)NE;
        float m  = (float)(g_sum[c] * invE);
        float m2 = (float)(g_sumsq[c] * invE);
        float g = gn[c], b = gn[C + c], ms = gn[2 * C + c];
        float var = m2 - 2.f * ms * m * m + ms * ms * m * m;
        float rs = rsqrtf(var + EPSV);
        g_alpha[c] = g * rs;
        g_beta[c]  = b - g * rs * ms * m;
        g_sum[c] = 0.0;
        g_sumsq[c] = 0.0;
    }
}

// pre-permute weights into mma B-fragment layout (fp16 packed), gmem-resident.
// Source W rows [K,N] row-major; value = Wa - Wb (Wb optional).
__global__ void k_trp(const float* __restrict__ Wa, const float* __restrict__ Wb,
                      uint32_t* __restrict__ out, int K, int N) {
    int tot = N * (K >> 1);
    int i = blockIdx.x * blockDim.x + threadIdx.x;
    for (; i < tot; i += gridDim.x * blockDim.x) {
        int n = i / (K >> 1);
        int kp = i - n * (K >> 1);
        int k = kp << 1;
        float v0 = Wa[(size_t)k * N + n], v1 = Wa[(size_t)(k + 1) * N + n];
        if (Wb) { v0 -= Wb[(size_t)k * N + n]; v1 -= Wb[(size_t)(k + 1) * N + n]; }
        int ch = k >> 5;
        int kpair = (k >> 1) & 15;
        int ksP = kpair >> 3, khi8 = (kpair >> 2) & 1, t4P = kpair & 3;
        int nblk = n >> 7, r = n & 127;
        int ni = r & 31, wn = r >> 5, nf = ni >> 3, gB = ni & 7;
        int slot = ((((wn << 1) + ksP) << 2) + nf) * 64 + (gB << 3) + (t4P << 1) + khi8;
        out[((size_t)nblk * (K >> 5) + ch) * 2048 + slot] = h2u(__floats2half2_rn(v0, v1));
    }
}

// ---------------- fp16 mma GEMM: A staged in smem (frag layout), B frags from gmem ----
// MODE 0: plain half A (raw copy). MODE 1: relu(affine(half A)). MODE 2: gather
// relu(affine(P[sdst]+Q[ssrc]+comb)). STATS: channel sum/sumsq of output.
template <int MODE, bool STATS>
__global__ void __launch_bounds__(256, 2)
wm_gemm(const __half* __restrict__ A, const __half* __restrict__ Qb,
        const uint32_t* __restrict__ Bp, const float* __restrict__ bias,
        const float* __restrict__ comb, __half* __restrict__ Co,
        int M, int K, int N) {
    __shared__ uint32_t sAu[2048];
    __shared__ float Ssum[128], Ssq[128];
    const int tid = threadIdx.x;
    const int w = tid >> 5, lane = tid & 31;
    const int g = lane >> 2, t4 = lane & 3;
    const int warpM = w & 1, warpN = w >> 1;
    const int m0 = blockIdx.x * 128, n0 = blockIdx.y * 128;

    if (STATS && tid < 128) { Ssum[tid] = 0.f; Ssq[tid] = 0.f; }

    float c[4][4][4];
#pragma unroll
    for (int i = 0; i < 4; i++)
#pragma unroll
        for (int j = 0; j < 4; j++)
#pragma unroll
            for (int k = 0; k < 4; k++) c[i][j][k] = 0.f;

    const int kpair = lane & 15, rhalf = lane >> 4;
    const int ksP = kpair >> 3, khi8 = (kpair >> 2) & 1, t4P = kpair & 3;
    const int nch = K >> 5;
    const uint32_t* Bbase = Bp + (size_t)blockIdx.y * nch * 2048;

    for (int ch = 0; ch < nch; ch++) {
        const int kg = (ch << 5) + (kpair << 1);
        float2 alv = make_float2(1.f, 1.f), bev = make_float2(0.f, 0.f);
        if (MODE >= 1) {
            alv = *(const float2*)(g_alpha + kg);
            bev = *(const float2*)(g_beta + kg);
            if (MODE == 2) {
                float2 cb = *(const float2*)(comb + kg);
                bev.x = fmaf(alv.x, cb.x, bev.x);
                bev.y = fmaf(alv.y, cb.y, bev.y);
            }
        }
#pragma unroll
        for (int j = 0; j < 8; j++) {
            const int r = (w << 4) + (j << 1) + rhalf;
            const int gm = m0 + r;
            uint32_t hu = 0;
            if (gm < M) {
                if (MODE == 0) {
                    hu = *(const uint32_t*)(A + (size_t)gm * K + kg);
                } else if (MODE == 1) {
                    float2 f = __half22float2(*(const __half2*)(A + (size_t)gm * K + kg));
                    hu = h2u(__floats2half2_rn(fmaxf(fmaf(alv.x, f.x, bev.x), 0.f),
                                               fmaxf(fmaf(alv.y, f.y, bev.y), 0.f)));
                } else {
                    int d = g_sdst[gm], s = g_ssrc[gm];
                    float2 fp = __half22float2(*(const __half2*)(A + (size_t)d * K + kg));
                    float2 fq = __half22float2(*(const __half2*)(Qb + (size_t)s * K + kg));
                    hu = h2u(__floats2half2_rn(fmaxf(fmaf(alv.x, fp.x + fq.x, bev.x), 0.f),
                                               fmaxf(fmaf(alv.y, fp.y + fq.y, bev.y), 0.f)));
                }
            }
            const int rb = r & 15, mf = (r >> 4) & 3, wm = r >> 6;
            const int gA = rb & 7, rowhi = rb >> 3;
            sAu[((((wm << 1) + ksP) << 2) + mf) * 128 + (gA << 4) + (t4P << 2) + rowhi + (khi8 << 1)] = hu;
        }
        __syncthreads();
        const uint4* A4 = (const uint4*)sAu;
        const uint2* B2 = (const uint2*)(Bbase + ch * 2048);
#pragma unroll
        for (int ks = 0; ks < 2; ks++) {
            uint4 af[4];
            uint2 bf[4];
#pragma unroll
            for (int mf = 0; mf < 4; mf++)
                af[mf] = A4[((((warpM << 1) + ks) << 2) + mf) * 32 + lane];
#pragma unroll
            for (int nf = 0; nf < 4; nf++)
                bf[nf] = B2[((((warpN << 1) + ks) << 2) + nf) * 32 + lane];
#pragma unroll
            for (int mf = 0; mf < 4; mf++)
#pragma unroll
                for (int nf = 0; nf < 4; nf++) {
                    asm volatile(
                        "mma.sync.aligned.m16n8k16.row.col.f32.f16.f16.f32 "
                        "{%0,%1,%2,%3}, {%4,%5,%6,%7}, {%8,%9}, {%0,%1,%2,%3};"
                        : "+f"(c[mf][nf][0]), "+f"(c[mf][nf][1]),
                          "+f"(c[mf][nf][2]), "+f"(c[mf][nf][3])
                        : "r"(af[mf].x), "r"(af[mf].y), "r"(af[mf].z), "r"(af[mf].w),
                          "r"(bf[nf].x), "r"(bf[nf].y));
                }
        }
        __syncthreads();
    }

#pragma unroll
    for (int mf = 0; mf < 4; mf++) {
        int r0 = m0 + warpM * 64 + mf * 16 + g;
#pragma unroll
        for (int nf = 0; nf < 4; nf++) {
            int colL = warpN * 32 + nf * 8 + 2 * t4;
            int colg = n0 + colL;
            float b0 = bias ? bias[colg] : 0.f;
            float b1 = bias ? bias[colg + 1] : 0.f;
            float v0 = c[mf][nf][0] + b0, v1 = c[mf][nf][1] + b1;
            float v2 = c[mf][nf][2] + b0, v3 = c[mf][nf][3] + b1;
            if (r0 < M)
                *(__half2*)(Co + (size_t)r0 * N + colg) = __floats2half2_rn(v0, v1);
            if (r0 + 8 < M)
                *(__half2*)(Co + (size_t)(r0 + 8) * N + colg) = __floats2half2_rn(v2, v3);
            if (STATS) {
                atomicAdd(&Ssum[colL], v0 + v2);
                atomicAdd(&Ssum[colL + 1], v1 + v3);
                atomicAdd(&Ssq[colL], fmaf(v0, v0, v2 * v2));
                atomicAdd(&Ssq[colL + 1], fmaf(v1, v1, v3 * v3));
            }
        }
    }
    if (STATS) {
        __syncthreads();
        if (tid < 128) {
            atomicAdd(&g_sum[n0 + tid], (double)Ssum[tid]);
            atomicAdd(&g_sumsq[n0 + tid], (double)Ssq[tid]);
        }
    }
}

// ---------------- segment-reduce aggregations (no atomics) ----------------
// mean_n relu(affine(H_e)) over CSR segment -> half node row (invdeg folded)
__global__ void k_agg_seg(const __half* __restrict__ H, __half* __restrict__ node, int logC) {
    const int sh = logC - 2;
    size_t tot = (size_t)NN << sh;
    for (size_t idx = (size_t)blockIdx.x * blockDim.x + threadIdx.x; idx < tot;
         idx += (size_t)gridDim.x * blockDim.x) {
        int n = (int)(idx >> sh);
        int cc = ((int)idx & ((1 << sh) - 1)) << 2;
        float4 al = *(const float4*)(g_alpha + cc);
        float4 be = *(const float4*)(g_beta + cc);
        int p0 = g_seg[n], p1 = g_seg[n + 1];
        float s0 = 0.f, s1 = 0.f, s2 = 0.f, s3 = 0.f;
        for (int p = p0; p < p1; p++) {
            uint2 hv = *(const uint2*)(H + ((size_t)p << logC) + cc);
            float2 f01 = __half22float2(*(__half2*)&hv.x);
            float2 f23 = __half22float2(*(__half2*)&hv.y);
            s0 += fmaxf(fmaf(al.x, f01.x, be.x), 0.f);
            s1 += fmaxf(fmaf(al.y, f01.y, be.y), 0.f);
            s2 += fmaxf(fmaf(al.z, f23.x, be.z), 0.f);
            s3 += fmaxf(fmaf(al.w, f23.y, be.w), 0.f);
        }
        float inv = g_invdeg[n];
        uint2 o;
        o.x = h2u(__floats2half2_rn(s0 * inv, s1 * inv));
        o.y = h2u(__floats2half2_rn(s2 * inv, s3 * inv));
        *(uint2*)(node + ((size_t)n << logC) + cc) = o;
    }
}

// block-3: mean_n relu(affine(P[n]+Q[src]+comb)) without edge GEMM
__global__ void k_agg_pq_seg(const __half* __restrict__ P, const __half* __restrict__ Qb,
                             const float* __restrict__ comb, __half* __restrict__ node) {
    size_t tot = (size_t)NN * 64;
    for (size_t idx = (size_t)blockIdx.x * blockDim.x + threadIdx.x; idx < tot;
         idx += (size_t)gridDim.x * blockDim.x) {
        int n = (int)(idx >> 6);
        int cc = ((int)idx & 63) << 2;
        float4 al = *(const float4*)(g_alpha + cc);
        float4 be = *(const float4*)(g_beta + cc);
        float4 cb = *(const float4*)(comb + cc);
        uint2 pv = *(const uint2*)(P + ((size_t)n << 8) + cc);
        float2 p01 = __half22float2(*(__half2*)&pv.x);
        float2 p23 = __half22float2(*(__half2*)&pv.y);
        float b0 = p01.x + cb.x, b1 = p01.y + cb.y, b2 = p23.x + cb.z, b3 = p23.y + cb.w;
        int p0 = g_seg[n], p1 = g_seg[n + 1];
        float s0 = 0.f, s1 = 0.f, s2 = 0.f, s3 = 0.f;
        for (int p = p0; p < p1; p++) {
            int s = g_ssrc[p];
            uint2 qv = *(const uint2*)(Qb + ((size_t)s << 8) + cc);
            float2 q01 = __half22float2(*(__half2*)&qv.x);
            float2 q23 = __half22float2(*(__half2*)&qv.y);
            s0 += fmaxf(fmaf(al.x, b0 + q01.x, be.x), 0.f);
            s1 += fmaxf(fmaf(al.y, b1 + q01.y, be.y), 0.f);
            s2 += fmaxf(fmaf(al.z, b2 + q23.x, be.z), 0.f);
            s3 += fmaxf(fmaf(al.w, b3 + q23.y, be.w), 0.f);
        }
        float inv = g_invdeg[n];
        uint2 o;
        o.x = h2u(__floats2half2_rn(s0 * inv, s1 * inv));
        o.y = h2u(__floats2half2_rn(s2 * inv, s3 * inv));
        *(uint2*)(node + ((size_t)n << 8) + cc) = o;
    }
}

// pool: mean over each graph's node range (batch sorted)
__global__ void k_pool_seg(const __half* __restrict__ h3) {
    int gph = blockIdx.x, t = threadIdx.x;
    int n0 = g_gseg[gph], n1 = g_gseg[gph + 1];
    float s = 0.f;
    for (int n = n0; n < n1; n++) s += __half2float(h3[(size_t)n * 256 + t]);
    g_pool[gph * 256 + t] = s / fmaxf((float)(n1 - n0), 1.f);
}

__global__ void k_head(const float* __restrict__ W1, const float* __restrict__ b1,
                       const float* __restrict__ W2, const float* __restrict__ b2,
                       float* __restrict__ out) {
    __shared__ float gv[256], hid[256], r0[256], r1[256];
    int r = blockIdx.x, t = threadIdx.x;
    gv[t] = g_pool[r * 256 + t];
    __syncthreads();
    float a = b1[t];
    for (int k = 0; k < 256; k++) a = fmaf(gv[k], W1[k * 256 + t], a);
    hid[t] = fmaxf(a, 0.f);
    __syncthreads();
    r0[t] = hid[t] * W2[t * 2 + 0];
    r1[t] = hid[t] * W2[t * 2 + 1];
    __syncthreads();
    for (int s = 128; s > 0; s >>= 1) {
        if (t < s) { r0[t] += r0[t + s]; r1[t] += r1[t + s]; }
        __syncthreads();
    }
    if (t == 0) {
        out[r * 2 + 0] = r0[0] + b2[0];
        out[r * 2 + 1] = r1[0] + b2[1];
    }
}

// ---------------- launcher ----------------
extern "C" void kernel_launch(void* const* d_in, const int* in_sizes, int n_in,
                              void* d_out, int out_size) {
    const float* x      = (const float*)d_in[0];
    const void*  ei     = d_in[1];
    const void*  bt     = d_in[2];
    const float* c1_w1  = (const float*)d_in[3];
    const float* c1_b1  = (const float*)d_in[4];
    const float* c1_gn1 = (const float*)d_in[5];
    const float* c1_w2  = (const float*)d_in[6];
    const float* c1_b2  = (const float*)d_in[7];
    const float* c1_gn2 = (const float*)d_in[8];
    const float* c1_w3  = (const float*)d_in[9];
    const float* c1_b3  = (const float*)d_in[10];
    const float* c1_gn3 = (const float*)d_in[11];
    const float* c2_w1  = (const float*)d_in[12];
    const float* c2_b1  = (const float*)d_in[13];
    const float* c2_gn1 = (const float*)d_in[14];
    const float* c2_w2  = (const float*)d_in[15];
    const float* c2_b2  = (const float*)d_in[16];
    const float* c2_gn2 = (const float*)d_in[17];
    const float* c3_w1  = (const float*)d_in[18];
    const float* c3_b1  = (const float*)d_in[19];
    const float* c3_gn1 = (const float*)d_in[20];
    const float* lw1    = (const float*)d_in[21];
    const float* lb1    = (const float*)d_in[22];
    const float* lw2    = (const float*)d_in[23];
    const float* lb2    = (const float*)d_in[24];
    float* out = (float*)d_out;
    (void)in_sizes; (void)n_in; (void)out_size;

    __half *pP, *pQ, *ph1, *ph2, *ph3, *pe0, *pe1;
    uint32_t *pwt, *pwtA, *pwtB;
    int *phist, *pghist;
    double *psum, *psq;
    cudaGetSymbolAddress((void**)&pP, g_P);
    cudaGetSymbolAddress((void**)&pQ, g_Q);
    cudaGetSymbolAddress((void**)&ph1, g_h1);
    cudaGetSymbolAddress((void**)&ph2, g_h2);
    cudaGetSymbolAddress((void**)&ph3, g_h3);
    cudaGetSymbolAddress((void**)&pe0, g_e0);
    cudaGetSymbolAddress((void**)&pe1, g_e1);
    cudaGetSymbolAddress((void**)&pwt, g_wtp);
    cudaGetSymbolAddress((void**)&pwtA, g_wtpA);
    cudaGetSymbolAddress((void**)&pwtB, g_wtpB);
    cudaGetSymbolAddress((void**)&phist, g_hist);
    cudaGetSymbolAddress((void**)&pghist, g_ghist);
    cudaGetSymbolAddress((void**)&psum, g_sum);
    cudaGetSymbolAddress((void**)&psq, g_sumsq);

    // setup: histograms + CSR sort
    cudaMemsetAsync(phist, 0, NN * sizeof(int));
    cudaMemsetAsync(pghist, 0, NG * sizeof(int));
    cudaMemsetAsync(psum, 0, 256 * sizeof(double));
    cudaMemsetAsync(psq, 0, 256 * sizeof(double));
    k_convert<<<1024, 256>>>(ei, bt);
    k_scan_nodes<<<1, 1024>>>();
    k_scan_graphs<<<1, 1024>>>();
    k_scatter<<<1024, 256>>>();

    const int ET = NE / 128;
    const int NT = (NN + 127) / 128;

    // block 1 (C=128, 3 layers)
    k_l1<<<2048, 128>>>(x, c1_w1);
    k_pqstats<<<2048, 128>>>(pP, pQ, c1_b1, 128);
    k_finalize<<<1, 256>>>(c1_gn1, 128);
    k_trp<<<64, 256>>>(c1_w2, nullptr, pwt, 128, 128);
    wm_gemm<2, true><<<dim3(ET, 1), 256>>>(pP, pQ, pwt, c1_b2, c1_b1, pe0, NE, 128, 128);
    k_finalize<<<1, 256>>>(c1_gn2, 128);
    k_trp<<<64, 256>>>(c1_w3, nullptr, pwtA, 128, 128);
    wm_gemm<1, true><<<dim3(ET, 1), 256>>>(pe0, nullptr, pwtA, c1_b3, nullptr, pe1, NE, 128, 128);
    k_finalize<<<1, 256>>>(c1_gn3, 128);
    k_agg_seg<<<4096, 256>>>(pe1, ph1, 7);

    // block 2 (C=256, 2 layers)
    k_trp<<<128, 256>>>(c2_w1, c2_w1 + 128 * 256, pwtA, 128, 256);
    k_trp<<<128, 256>>>(c2_w1 + 128 * 256, nullptr, pwtB, 128, 256);
    wm_gemm<0, false><<<dim3(NT, 2), 256>>>(ph1, nullptr, pwtA, nullptr, nullptr, pP, NN, 128, 256);
    wm_gemm<0, false><<<dim3(NT, 2), 256>>>(ph1, nullptr, pwtB, nullptr, nullptr, pQ, NN, 128, 256);
    k_pqstats<<<2048, 256>>>(pP, pQ, c2_b1, 256);
    k_finalize<<<1, 256>>>(c2_gn1, 256);
    k_trp<<<256, 256>>>(c2_w2, nullptr, pwt, 256, 256);
    wm_gemm<2, true><<<dim3(ET, 2), 256>>>(pP, pQ, pwt, c2_b2, c2_b1, pe0, NE, 256, 256);
    k_finalize<<<1, 256>>>(c2_gn2, 256);
    k_agg_seg<<<8192, 256>>>(pe0, ph2, 8);

    // block 3 (C=256, 1 layer — no edge GEMM)
    k_trp<<<256, 256>>>(c3_w1, c3_w1 + 256 * 256, pwtA, 256, 256);
    k_trp<<<256, 256>>>(c3_w1 + 256 * 256, nullptr, pwtB, 256, 256);
    wm_gemm<0, false><<<dim3(NT, 2), 256>>>(ph2, nullptr, pwtA, nullptr, nullptr, pP, NN, 256, 256);
    wm_gemm<0, false><<<dim3(NT, 2), 256>>>(ph2, nullptr, pwtB, nullptr, nullptr, pQ, NN, 256, 256);
    k_pqstats<<<2048, 256>>>(pP, pQ, c3_b1, 256);
    k_finalize<<<1, 256>>>(c3_gn1, 256);
    k_agg_pq_seg<<<8192, 256>>>(pP, pQ, c3_b1, ph3);

    // pool + head
    k_pool_seg<<<NG, 256>>>(ph3);
    k_head<<<NG, 256>>>(lw1, lb1, lw2, lb2, out);
}